// round 10
// baseline (speedup 1.0000x reference)
#include <cuda_runtime.h>
#include <math.h>
#include <stdint.h>

#define BATCH 8
#define SEQ   2048
#define FDIM  512
#define DDIM  512
#define MTOT  (BATCH * SEQ)   // 16384

// ---------------- scratch (__device__ globals; no allocs allowed) ----------
__device__ __align__(16) int8_t g_xpe_h[(size_t)MTOT * FDIM];
__device__ __align__(16) int8_t g_xpe_l[(size_t)MTOT * FDIM];
__device__ float  g_sx[MTOT];
__device__ __align__(16) int8_t g_Wt_h[3 * FDIM * DDIM];   // [z][n][k]
__device__ __align__(16) int8_t g_Wt_l[3 * FDIM * DDIM];
__device__ float  g_sw[3 * DDIM];
__device__ float  g_Q[(size_t)MTOT * DDIM];  // fp32 intermediates
__device__ float  g_K[(size_t)MTOT * DDIM];
__device__ float  g_V[(size_t)MTOT * DDIM];
__device__ __align__(16) int8_t g_Qh[(size_t)MTOT * DDIM];
__device__ __align__(16) int8_t g_Ql[(size_t)MTOT * DDIM];
__device__ __align__(16) int8_t g_Kh[(size_t)MTOT * DDIM];
__device__ __align__(16) int8_t g_Kl[(size_t)MTOT * DDIM];
__device__ float  g_sq[MTOT];
__device__ float  g_sk[MTOT];
__device__ float  g_vpart[8 * 32 * DDIM];
__device__ float  g_sv[8 * DDIM];
__device__ __align__(16) int8_t g_Vt_h[(size_t)MTOT * DDIM];  // [b][d][j]
__device__ __align__(16) int8_t g_Vt_l[(size_t)MTOT * DDIM];
__device__ float  g_scores[(size_t)BATCH * SEQ * SEQ];
__device__ __align__(16) int8_t g_attn_h[(size_t)BATCH * SEQ * SEQ];
__device__ __align__(16) int8_t g_attn_l[(size_t)BATCH * SEQ * SEQ];
__device__ float  g_sattn[MTOT];

// ---------------- PTX helpers ----------------------------------------------
__device__ __forceinline__ uint32_t s2u(const void* p) {
    return (uint32_t)__cvta_generic_to_shared(p);
}
__device__ __forceinline__ void cpa16(uint32_t dst, const void* src) {
    asm volatile("cp.async.cg.shared.global [%0], [%1], 16;\n" :: "r"(dst), "l"(src));
}
#define CP_COMMIT()  asm volatile("cp.async.commit_group;\n" ::: "memory")
#define CP_WAIT2()   asm volatile("cp.async.wait_group 2;\n" ::: "memory")

#define LDM4(r, addr) \
    asm volatile("ldmatrix.sync.aligned.m8n8.x4.shared.b16 {%0,%1,%2,%3}, [%4];" \
                 : "=r"((r)[0]), "=r"((r)[1]), "=r"((r)[2]), "=r"((r)[3]) : "r"(addr))

#define IMMA(d, a, b0, b1) \
    asm volatile("mma.sync.aligned.m16n8k32.row.col.s32.s8.s8.s32 " \
                 "{%0,%1,%2,%3}, {%4,%5,%6,%7}, {%8,%9}, {%0,%1,%2,%3};" \
                 : "+r"((d)[0]), "+r"((d)[1]), "+r"((d)[2]), "+r"((d)[3]) \
                 : "r"((a)[0]), "r"((a)[1]), "r"((a)[2]), "r"((a)[3]), \
                   "r"(b0), "r"(b1))

// quantize v to h*256 + l with t = v*inv_s, |t| <= ~32512
__device__ __forceinline__ void q16(float v, float inv_s, int8_t* h, int8_t* l) {
    float tq = v * inv_s;
    float hf = rintf(tq * 0.00390625f);
    hf = fminf(fmaxf(hf, -127.f), 127.f);
    float lf = rintf(tq - 256.f * hf);
    lf = fminf(fmaxf(lf, -128.f), 127.f);
    *h = (int8_t)hf;
    *l = (int8_t)lf;
}

// ---------------- GEMM: CTA 128x128, K-chunk 64, int8x3, IMMA --------------
// Warp grid 2(M) x 4(N); warp tile 64x32. Rows: 64 int8 + 16B pad = 80B.
#define OFF_AL     10240
#define OFF_BH     20480
#define OFF_BL     30720
#define STAGE_B    40960
#define SMEM_TOTAL (3 * STAGE_B)   // 122880

__device__ __forceinline__ void ld_stage(uint32_t sb,
    const int8_t* Ah, const int8_t* Al,
    const int8_t* Bh, const int8_t* Bl,
    int K, int k0, int tid)
{
#pragma unroll
    for (int i = 0; i < 2; i++) {
        int ci = tid + i * 256;
        int r = ci >> 2, c = ci & 3;
        size_t ge = (size_t)r * K + k0 + c * 16;
        uint32_t so = r * 80 + c * 16;
        cpa16(sb + so,          Ah + ge);
        cpa16(sb + OFF_AL + so, Al + ge);
        cpa16(sb + OFF_BH + so, Bh + ge);
        cpa16(sb + OFF_BL + so, Bl + ge);
    }
}

__device__ __forceinline__ void gemm_core_i8(
    const int8_t* __restrict__ Ah, const int8_t* __restrict__ Al,
    const int8_t* __restrict__ Bh, const int8_t* __restrict__ Bl,
    const float* __restrict__ sA, const float* __restrict__ sB,
    int K, float alpha, float* __restrict__ C, int ldC)
{
    extern __shared__ __align__(128) char sm[];
    const uint32_t smb = s2u(sm);
    const int tid = threadIdx.x;
    const int w = tid >> 5, lane = tid & 31;
    const int wr = w & 1, wc = w >> 1;         // 2 (M) x 4 (N)
    const int q = lane & 7, sel = lane >> 3;
    const int g = lane >> 2, t = lane & 3;

    uint32_t aoff[4], boff[2];
#pragma unroll
    for (int mt = 0; mt < 4; mt++)
        aoff[mt] = (uint32_t)(wr * 64 + mt * 16 + (sel & 1) * 8 + q) * 80
                 + (uint32_t)(sel >> 1) * 16;
#pragma unroll
    for (int nb = 0; nb < 2; nb++)
        boff[nb] = (uint32_t)(wc * 32 + nb * 16 + (sel >> 1) * 8 + q) * 80
                 + (uint32_t)(sel & 1) * 16;

    const int n = K >> 6;   // K / 64 chunks

    ld_stage(smb,           Ah, Al, Bh, Bl, K, 0,  tid); CP_COMMIT();
    ld_stage(smb + STAGE_B, Ah, Al, Bh, Bl, K, 64, tid); CP_COMMIT();

    int hh[4][4][4], cr[4][4][4];
#pragma unroll
    for (int mt = 0; mt < 4; mt++)
#pragma unroll
        for (int nt = 0; nt < 4; nt++)
#pragma unroll
            for (int r = 0; r < 4; r++) { hh[mt][nt][r] = 0; cr[mt][nt][r] = 0; }

    for (int i = 0; i < n; i++) {
        __syncthreads();
        if (i + 2 < n)
            ld_stage(smb + ((i + 2) % 3) * STAGE_B, Ah, Al, Bh, Bl, K,
                     (i + 2) * 64, tid);
        CP_COMMIT();
        CP_WAIT2();
        __syncthreads();

        const uint32_t sb = smb + (i % 3) * STAGE_B;
#pragma unroll
        for (int ks = 0; ks < 2; ks++) {
            uint32_t ah[4][4], al[4][4], bh[2][4], bl[2][4];
#pragma unroll
            for (int mt = 0; mt < 4; mt++) {
                uint32_t ad = sb + aoff[mt] + ks * 32;
                LDM4(ah[mt], ad);
                LDM4(al[mt], ad + OFF_AL);
            }
#pragma unroll
            for (int nb = 0; nb < 2; nb++) {
                uint32_t bd = sb + OFF_BH + boff[nb] + ks * 32;
                LDM4(bh[nb], bd);
                LDM4(bl[nb], bd + (OFF_BL - OFF_BH));
            }
            // term-major: hi*hi -> acc_hh ; hi*lo, lo*hi -> acc_cr
#pragma unroll
            for (int mt = 0; mt < 4; mt++)
#pragma unroll
                for (int nt = 0; nt < 4; nt++) {
                    const uint32_t* B0 = &bh[nt >> 1][(nt & 1) * 2];
                    IMMA(hh[mt][nt], ah[mt], B0[0], B0[1]);
                }
#pragma unroll
            for (int mt = 0; mt < 4; mt++)
#pragma unroll
                for (int nt = 0; nt < 4; nt++) {
                    const uint32_t* B1 = &bl[nt >> 1][(nt & 1) * 2];
                    IMMA(cr[mt][nt], ah[mt], B1[0], B1[1]);
                }
#pragma unroll
            for (int mt = 0; mt < 4; mt++)
#pragma unroll
                for (int nt = 0; nt < 4; nt++) {
                    const uint32_t* B0 = &bh[nt >> 1][(nt & 1) * 2];
                    IMMA(cr[mt][nt], al[mt], B0[0], B0[1]);
                }
        }
    }

    // epilogue: out = alpha * sA[i] * sB[j] * (65536*hh + 256*cr)
#pragma unroll
    for (int mt = 0; mt < 4; mt++)
#pragma unroll
        for (int nt = 0; nt < 4; nt++) {
            int r0 = wr * 64 + mt * 16 + g;
            int c0 = wc * 32 + nt * 8 + 2 * t;
            float sa0 = alpha * sA[r0], sa1 = alpha * sA[r0 + 8];
            float sb0 = sB[c0], sb1 = sB[c0 + 1];
            float f0 = 65536.f * (float)hh[mt][nt][0] + 256.f * (float)cr[mt][nt][0];
            float f1 = 65536.f * (float)hh[mt][nt][1] + 256.f * (float)cr[mt][nt][1];
            float f2 = 65536.f * (float)hh[mt][nt][2] + 256.f * (float)cr[mt][nt][2];
            float f3 = 65536.f * (float)hh[mt][nt][3] + 256.f * (float)cr[mt][nt][3];
            float2 v0; v0.x = f0 * sa0 * sb0; v0.y = f1 * sa0 * sb1;
            float2 v1; v1.x = f2 * sa1 * sb0; v1.y = f3 * sa1 * sb1;
            *(float2*)(C + (size_t)r0 * ldC + c0)       = v0;
            *(float2*)(C + (size_t)(r0 + 8) * ldC + c0) = v1;
        }
}

// ---------------- GEMM wrapper kernels -------------------------------------
__global__ void __launch_bounds__(256, 1) k_gemm_proj() {
    const int z = blockIdx.z;
    const size_t a0 = (size_t)blockIdx.y * 128 * FDIM;
    const size_t b0 = ((size_t)z * DDIM + blockIdx.x * 128) * FDIM;
    float* Cz = (z == 0) ? g_Q : (z == 1) ? g_K : g_V;
    const size_t c0 = (size_t)blockIdx.y * 128 * DDIM + blockIdx.x * 128;
    gemm_core_i8(g_xpe_h + a0, g_xpe_l + a0, g_Wt_h + b0, g_Wt_l + b0,
                 g_sx + blockIdx.y * 128, g_sw + z * DDIM + blockIdx.x * 128,
                 FDIM, 1.0f, Cz + c0, DDIM);
}

__global__ void __launch_bounds__(256, 1) k_gemm_scores() {
    const size_t b = blockIdx.z;
    const size_t a0 = (b * SEQ + blockIdx.y * 128) * DDIM;
    const size_t b0 = (b * SEQ + blockIdx.x * 128) * DDIM;
    const size_t c0 = b * SEQ * SEQ + (size_t)blockIdx.y * 128 * SEQ + blockIdx.x * 128;
    gemm_core_i8(g_Qh + a0, g_Ql + a0, g_Kh + b0, g_Kl + b0,
                 g_sq + b * SEQ + blockIdx.y * 128, g_sk + b * SEQ + blockIdx.x * 128,
                 DDIM, 0.04419417382415922f, g_scores + c0, SEQ);
}

__global__ void __launch_bounds__(256, 1) k_gemm_av(float* __restrict__ out) {
    const size_t b = blockIdx.z;
    const size_t a0 = b * SEQ * SEQ + (size_t)blockIdx.y * 128 * SEQ;
    const size_t b0 = (b * DDIM + blockIdx.x * 128) * SEQ;
    const size_t c0 = (b * SEQ + blockIdx.y * 128) * DDIM + blockIdx.x * 128;
    gemm_core_i8(g_attn_h + a0, g_attn_l + a0, g_Vt_h + b0, g_Vt_l + b0,
                 g_sattn + b * SEQ + blockIdx.y * 128, g_sv + b * DDIM + blockIdx.x * 128,
                 SEQ, 1.0f, out + c0, DDIM);
}

// ---------------- aux kernels ----------------------------------------------
// block = one row of 512: x + PE, row max, quantize
__global__ void __launch_bounds__(512) k_addpe_quant(const float* __restrict__ x) {
    const int row = blockIdx.x;               // b*2048 + s
    const int s = row & (SEQ - 1);
    const int f = threadIdx.x;
    const size_t idx = (size_t)row * FDIM + f;
    float e     = (float)(f & ~1) * (1.0f / (float)FDIM);
    float denom = powf(10000.0f, e);
    float angle = (float)s / denom;
    double r = fmod((double)angle, 6.283185307179586476925286766559);
    float a = (float)r;
    float pe = (f & 1) ? cosf(a) : sinf(a);
    float v = x[idx] + pe;

    __shared__ float sh[16];
    float m = fabsf(v);
#pragma unroll
    for (int o = 16; o > 0; o >>= 1) m = fmaxf(m, __shfl_xor_sync(~0u, m, o));
    if ((f & 31) == 0) sh[f >> 5] = m;
    __syncthreads();
    m = sh[0];
#pragma unroll
    for (int ww = 1; ww < 16; ww++) m = fmaxf(m, sh[ww]);

    float inv = (m > 0.f) ? 32512.f / m : 0.f;
    int8_t h, l;
    q16(v, inv, &h, &l);
    g_xpe_h[idx] = h;
    g_xpe_l[idx] = l;
    if (f == 0) g_sx[row] = m * (1.f / 32512.f);
}

// block = one W column (one Wt row): Wt[z][n][k] = W[z][k][n]
__global__ void __launch_bounds__(256) k_quantW(const float* __restrict__ Wq,
                                                const float* __restrict__ Wk,
                                                const float* __restrict__ Wv) {
    const int nn = blockIdx.x, z = blockIdx.y;
    const float* W = (z == 0) ? Wq : (z == 1) ? Wk : Wv;
    const int tid = threadIdx.x;
    float v0 = W[(size_t)tid * DDIM + nn];
    float v1 = W[(size_t)(tid + 256) * DDIM + nn];
    __shared__ float sh[8];
    float m = fmaxf(fabsf(v0), fabsf(v1));
#pragma unroll
    for (int o = 16; o > 0; o >>= 1) m = fmaxf(m, __shfl_xor_sync(~0u, m, o));
    if ((tid & 31) == 0) sh[tid >> 5] = m;
    __syncthreads();
    m = sh[0];
#pragma unroll
    for (int ww = 1; ww < 8; ww++) m = fmaxf(m, sh[ww]);
    float inv = (m > 0.f) ? 32512.f / m : 0.f;
    const size_t base = ((size_t)z * DDIM + nn) * FDIM;
    int8_t h, l;
    q16(v0, inv, &h, &l); g_Wt_h[base + tid] = h;       g_Wt_l[base + tid] = l;
    q16(v1, inv, &h, &l); g_Wt_h[base + tid + 256] = h; g_Wt_l[base + tid + 256] = l;
    if (tid == 0) g_sw[z * DDIM + nn] = m * (1.f / 32512.f);
}

// per-row quant of Q (y=0) and K (y=1), fp32 -> int8 planes
__global__ void __launch_bounds__(256) k_rowquant() {
    const int row = blockIdx.x;
    const int which = blockIdx.y;
    const float* src = which ? g_K : g_Q;
    int8_t* dh = which ? g_Kh : g_Qh;
    int8_t* dl = which ? g_Kl : g_Ql;
    float* ds  = which ? g_sk : g_sq;
    const int tid = threadIdx.x;
    const size_t base = (size_t)row * DDIM;
    float v0 = src[base + tid], v1 = src[base + tid + 256];
    __shared__ float sh[8];
    float m = fmaxf(fabsf(v0), fabsf(v1));
#pragma unroll
    for (int o = 16; o > 0; o >>= 1) m = fmaxf(m, __shfl_xor_sync(~0u, m, o));
    if ((tid & 31) == 0) sh[tid >> 5] = m;
    __syncthreads();
    m = sh[0];
#pragma unroll
    for (int ww = 1; ww < 8; ww++) m = fmaxf(m, sh[ww]);
    float inv = (m > 0.f) ? 32512.f / m : 0.f;
    int8_t h, l;
    q16(v0, inv, &h, &l); dh[base + tid] = h;       dl[base + tid] = l;
    q16(v1, inv, &h, &l); dh[base + tid + 256] = h; dl[base + tid + 256] = l;
    if (tid == 0) ds[row] = m * (1.f / 32512.f);
}

// per-(b,d) max of |V| in two stages
__global__ void __launch_bounds__(512) k_vmax_part() {
    const int c = blockIdx.x, b = blockIdx.y;
    const int d = threadIdx.x;
    float m = 0.f;
#pragma unroll 4
    for (int jj = 0; jj < 64; jj++) {
        int j = c * 64 + jj;
        m = fmaxf(m, fabsf(g_V[((size_t)b * SEQ + j) * DDIM + d]));
    }
    g_vpart[((size_t)b * 32 + c) * DDIM + d] = m;
}
__global__ void __launch_bounds__(512) k_vmax_red() {
    const int b = blockIdx.x, d = threadIdx.x;
    float m = 0.f;
#pragma unroll
    for (int c = 0; c < 32; c++)
        m = fmaxf(m, g_vpart[((size_t)b * 32 + c) * DDIM + d]);
    g_sv[b * DDIM + d] = m * (1.f / 32512.f);
}

// transpose V (fp32) -> Vt int8 planes with per-d scales
__global__ void __launch_bounds__(256) k_transV_quant() {
    __shared__ float tsm[32][33];
    const int b = blockIdx.z;
    const int d0 = blockIdx.x * 32, j0 = blockIdx.y * 32;
    const int tx = threadIdx.x & 31, ty = threadIdx.x >> 5;
#pragma unroll
    for (int i = 0; i < 32; i += 8)
        tsm[ty + i][tx] = g_V[((size_t)b * SEQ + j0 + ty + i) * DDIM + d0 + tx];
    __syncthreads();
#pragma unroll
    for (int i = 0; i < 32; i += 8) {
        int d = d0 + ty + i;
        float s = g_sv[b * DDIM + d];
        float inv = (s > 0.f) ? 1.f / s : 0.f;
        float v = tsm[tx][ty + i];
        int8_t h, l;
        q16(v, inv, &h, &l);
        size_t off = ((size_t)b * DDIM + d) * SEQ + j0 + tx;
        g_Vt_h[off] = h;
        g_Vt_l[off] = l;
    }
}

// softmax over 2048 cols + int8 quant (row max of attn = 1/sum exactly)
__global__ void __launch_bounds__(256) k_softmax_quant() {
    const int row = blockIdx.x;
    const size_t rowoff = (size_t)row * SEQ;
    const float* p = g_scores + rowoff;
    const int tid = threadIdx.x;
    float v[8];
    float m = -1e30f;
#pragma unroll
    for (int i = 0; i < 8; i++) {
        v[i] = p[tid + i * 256];
        m = fmaxf(m, v[i]);
    }
    __shared__ float sh[8];
#pragma unroll
    for (int o = 16; o > 0; o >>= 1) m = fmaxf(m, __shfl_xor_sync(~0u, m, o));
    if ((tid & 31) == 0) sh[tid >> 5] = m;
    __syncthreads();
    m = sh[0];
#pragma unroll
    for (int ww = 1; ww < 8; ww++) m = fmaxf(m, sh[ww]);

    float s = 0.0f;
#pragma unroll
    for (int i = 0; i < 8; i++) {
        v[i] = expf(v[i] - m);
        s += v[i];
    }
#pragma unroll
    for (int o = 16; o > 0; o >>= 1) s += __shfl_xor_sync(~0u, s, o);
    __syncthreads();
    if ((tid & 31) == 0) sh[tid >> 5] = s;
    __syncthreads();
    s = 0.0f;
#pragma unroll
    for (int ww = 0; ww < 8; ww++) s += sh[ww];
    const float inv = 1.0f / s;
    // attn_i = v[i]*inv; row max attn = inv; t = attn/(inv/32512) = 32512*v[i]
#pragma unroll
    for (int i = 0; i < 8; i++) {
        float tq = 32512.f * v[i];
        float hf = rintf(tq * 0.00390625f);
        hf = fminf(fmaxf(hf, -127.f), 127.f);
        float lf = rintf(tq - 256.f * hf);
        lf = fminf(fmaxf(lf, -128.f), 127.f);
        g_attn_h[rowoff + tid + i * 256] = (int8_t)hf;
        g_attn_l[rowoff + tid + i * 256] = (int8_t)lf;
    }
    if (tid == 0) g_sattn[row] = inv * (1.f / 32512.f);
}

// ---------------- launch ----------------------------------------------------
extern "C" void kernel_launch(void* const* d_in, const int* in_sizes, int n_in,
                              void* d_out, int out_size)
{
    const float* x  = (const float*)d_in[0];
    const float* Wq = (const float*)d_in[1];
    const float* Wk = (const float*)d_in[2];
    const float* Wv = (const float*)d_in[3];
    float* out = (float*)d_out;

    cudaFuncSetAttribute(k_gemm_proj,   cudaFuncAttributeMaxDynamicSharedMemorySize, SMEM_TOTAL);
    cudaFuncSetAttribute(k_gemm_scores, cudaFuncAttributeMaxDynamicSharedMemorySize, SMEM_TOTAL);
    cudaFuncSetAttribute(k_gemm_av,     cudaFuncAttributeMaxDynamicSharedMemorySize, SMEM_TOTAL);

    k_addpe_quant<<<MTOT, 512>>>(x);
    k_quantW<<<dim3(DDIM, 3), 256>>>(Wq, Wk, Wv);
    k_gemm_proj<<<dim3(DDIM / 128, MTOT / 128, 3), 256, SMEM_TOTAL>>>();
    k_rowquant<<<dim3(MTOT, 2), 256>>>();
    k_vmax_part<<<dim3(32, BATCH), 512>>>();
    k_vmax_red<<<BATCH, 512>>>();
    k_transV_quant<<<dim3(DDIM / 32, SEQ / 32, BATCH), 256>>>();
    k_gemm_scores<<<dim3(SEQ / 128, SEQ / 128, BATCH), 256, SMEM_TOTAL>>>();
    k_softmax_quant<<<MTOT, 256>>>();
    k_gemm_av<<<dim3(DDIM / 128, SEQ / 128, BATCH), 256, SMEM_TOTAL>>>(out);
}

// round 11
// speedup vs baseline: 2.4671x; 2.4671x over previous
#include <cuda_runtime.h>
#include <cuda_bf16.h>
#include <math.h>
#include <stdint.h>

#define BATCH 8
#define SEQ   2048
#define FDIM  512
#define DDIM  512
#define MTOT  (BATCH * SEQ)   // 16384

// ---------------- scratch (__device__ globals; no allocs allowed) ----------
__device__ __nv_bfloat16 g_xpe_h[(size_t)MTOT * FDIM];
__device__ __nv_bfloat16 g_xpe_l[(size_t)MTOT * FDIM];
__device__ __nv_bfloat16 g_Wt_h[3 * FDIM * DDIM];      // [z][n][k] (W transposed)
__device__ __nv_bfloat16 g_Wt_l[3 * FDIM * DDIM];
__device__ __nv_bfloat16 g_Q_h[(size_t)MTOT * DDIM];
__device__ __nv_bfloat16 g_Q_l[(size_t)MTOT * DDIM];
__device__ __nv_bfloat16 g_K_h[(size_t)MTOT * DDIM];
__device__ __nv_bfloat16 g_K_l[(size_t)MTOT * DDIM];
__device__ __nv_bfloat16 g_V_h[(size_t)MTOT * DDIM];
__device__ __nv_bfloat16 g_V_l[(size_t)MTOT * DDIM];
__device__ __nv_bfloat16 g_Vt_h[(size_t)MTOT * DDIM];  // [b][d][j]
__device__ __nv_bfloat16 g_Vt_l[(size_t)MTOT * DDIM];
__device__ float         g_scores[(size_t)BATCH * SEQ * SEQ];     // 134MB
__device__ __nv_bfloat16 g_attn_h[(size_t)BATCH * SEQ * SEQ];
__device__ __nv_bfloat16 g_attn_l[(size_t)BATCH * SEQ * SEQ];

// ---------------- PTX helpers ----------------------------------------------
__device__ __forceinline__ uint32_t s2u(const void* p) {
    return (uint32_t)__cvta_generic_to_shared(p);
}
__device__ __forceinline__ void cpa16(uint32_t dst, const void* src) {
    asm volatile("cp.async.cg.shared.global [%0], [%1], 16;\n" :: "r"(dst), "l"(src));
}
#define CP_COMMIT()  asm volatile("cp.async.commit_group;\n" ::: "memory")
#define CP_WAIT2()   asm volatile("cp.async.wait_group 2;\n" ::: "memory")

#define LDM4(r, addr) \
    asm volatile("ldmatrix.sync.aligned.m8n8.x4.shared.b16 {%0,%1,%2,%3}, [%4];" \
                 : "=r"((r)[0]), "=r"((r)[1]), "=r"((r)[2]), "=r"((r)[3]) : "r"(addr))

#define MMA16816(d, a, b0, b1) \
    asm volatile("mma.sync.aligned.m16n8k16.row.col.f32.bf16.bf16.f32 " \
                 "{%0,%1,%2,%3}, {%4,%5,%6,%7}, {%8,%9}, {%0,%1,%2,%3};" \
                 : "+f"((d)[0]), "+f"((d)[1]), "+f"((d)[2]), "+f"((d)[3]) \
                 : "r"((a)[0]), "r"((a)[1]), "r"((a)[2]), "r"((a)[3]), \
                   "r"(b0), "r"(b1))

// ---------------- GEMM: CTA 128x128, K-chunk 32, bf16x3, HMMA --------------
// smem per stage: 4 planes (Ah, Al, Bh, Bl), each 128 rows x 80B (32 bf16 + pad)
#define PLANE_B    10240
#define STAGE_B    40960
#define SMEM_TOTAL (4 * STAGE_B)   // 163840

__device__ __forceinline__ void ld_stage(uint32_t sb,
    const __nv_bfloat16* Ah, const __nv_bfloat16* Al,
    const __nv_bfloat16* Bh, const __nv_bfloat16* Bl,
    int K, int k0, int tid)
{
#pragma unroll
    for (int i = 0; i < 2; i++) {
        int ci = tid + i * 256;
        int r = ci >> 2, c = ci & 3;
        size_t ge = (size_t)r * K + k0 + c * 8;   // bf16 element offset
        uint32_t so = r * 80 + c * 16;
        cpa16(sb + so,               Ah + ge);
        cpa16(sb + PLANE_B + so,     Al + ge);
        cpa16(sb + 2 * PLANE_B + so, Bh + ge);
        cpa16(sb + 3 * PLANE_B + so, Bl + ge);
    }
}

// EPI 0: fp32 C with alpha.  EPI 1: bf16 hi/lo split planes.
template <int EPI>
__device__ __forceinline__ void gemm_core(
    const __nv_bfloat16* __restrict__ Ah, const __nv_bfloat16* __restrict__ Al,
    const __nv_bfloat16* __restrict__ Bh, const __nv_bfloat16* __restrict__ Bl,
    int K, float alpha,
    float* __restrict__ C, int ldC,
    __nv_bfloat16* __restrict__ Ch, __nv_bfloat16* __restrict__ Cl)
{
    extern __shared__ __align__(128) char sm[];
    const uint32_t smb = s2u(sm);
    const int tid = threadIdx.x;
    const int w = tid >> 5, lane = tid & 31;
    const int wr = w & 1, wc = w >> 1;         // warp grid 2 (M) x 4 (N)
    const int q = lane & 7, sel = lane >> 3;   // ldmatrix addressing
    const int g = lane >> 2, t = lane & 3;     // fragment addressing

    // per-thread ldmatrix smem byte offsets (within plane); ks adds ks*32
    uint32_t aoff[4], boff[2];
#pragma unroll
    for (int mt = 0; mt < 4; mt++)
        aoff[mt] = (uint32_t)(wr * 64 + mt * 16 + (sel & 1) * 8 + q) * 80
                 + (uint32_t)(sel >> 1) * 16;
#pragma unroll
    for (int nb = 0; nb < 2; nb++)
        boff[nb] = (uint32_t)(wc * 32 + nb * 16 + (sel >> 1) * 8 + q) * 80
                 + (uint32_t)(sel & 1) * 16;

    const int n = K >> 5;   // K / 32 chunks

    ld_stage(smb,           Ah, Al, Bh, Bl, K, 0,  tid); CP_COMMIT();
    ld_stage(smb + STAGE_B, Ah, Al, Bh, Bl, K, 32, tid); CP_COMMIT();

    float acc[4][4][4];
#pragma unroll
    for (int mt = 0; mt < 4; mt++)
#pragma unroll
        for (int nt = 0; nt < 4; nt++)
#pragma unroll
            for (int r = 0; r < 4; r++) acc[mt][nt][r] = 0.0f;

    for (int i = 0; i < n; i++) {
        if (i + 2 < n)
            ld_stage(smb + ((i + 2) & 3) * STAGE_B, Ah, Al, Bh, Bl, K,
                     (i + 2) * 32, tid);
        CP_COMMIT();
        CP_WAIT2();
        __syncthreads();

        const uint32_t sb = smb + (i & 3) * STAGE_B;
#pragma unroll
        for (int ks = 0; ks < 2; ks++) {
            uint32_t ah[4][4], al[4][4], bh[2][4], bl[2][4];
#pragma unroll
            for (int mt = 0; mt < 4; mt++) {
                uint32_t ad = sb + aoff[mt] + ks * 32;
                LDM4(ah[mt], ad);
                LDM4(al[mt], ad + PLANE_B);
            }
#pragma unroll
            for (int nb = 0; nb < 2; nb++) {
                uint32_t bd = sb + 2 * PLANE_B + boff[nb] + ks * 32;
                LDM4(bh[nb], bd);
                LDM4(bl[nb], bd + PLANE_B);
            }
            // term-major issue order keeps dependent MMAs 16 apart
#pragma unroll
            for (int mt = 0; mt < 4; mt++)
#pragma unroll
                for (int nt = 0; nt < 4; nt++) {
                    const uint32_t* B0 = &bh[nt >> 1][(nt & 1) * 2];
                    MMA16816(acc[mt][nt], ah[mt], B0[0], B0[1]);
                }
#pragma unroll
            for (int mt = 0; mt < 4; mt++)
#pragma unroll
                for (int nt = 0; nt < 4; nt++) {
                    const uint32_t* B1 = &bl[nt >> 1][(nt & 1) * 2];
                    MMA16816(acc[mt][nt], ah[mt], B1[0], B1[1]);
                }
#pragma unroll
            for (int mt = 0; mt < 4; mt++)
#pragma unroll
                for (int nt = 0; nt < 4; nt++) {
                    const uint32_t* B0 = &bh[nt >> 1][(nt & 1) * 2];
                    MMA16816(acc[mt][nt], al[mt], B0[0], B0[1]);
                }
        }
    }

    // epilogue
#pragma unroll
    for (int mt = 0; mt < 4; mt++)
#pragma unroll
        for (int nt = 0; nt < 4; nt++) {
            int r0 = wr * 64 + mt * 16 + g;
            int c0 = wc * 32 + nt * 8 + 2 * t;
            if (EPI == 0) {
                float2 v0, v1;
                v0.x = alpha * acc[mt][nt][0]; v0.y = alpha * acc[mt][nt][1];
                v1.x = alpha * acc[mt][nt][2]; v1.y = alpha * acc[mt][nt][3];
                *(float2*)(C + (size_t)r0 * ldC + c0)       = v0;
                *(float2*)(C + (size_t)(r0 + 8) * ldC + c0) = v1;
            } else {
#pragma unroll
                for (int hh = 0; hh < 2; hh++) {
                    float v0 = acc[mt][nt][2 * hh + 0];
                    float v1 = acc[mt][nt][2 * hh + 1];
                    __nv_bfloat16 h0 = __float2bfloat16(v0);
                    __nv_bfloat16 h1 = __float2bfloat16(v1);
                    __nv_bfloat16 l0 = __float2bfloat16(v0 - __bfloat162float(h0));
                    __nv_bfloat16 l1 = __float2bfloat16(v1 - __bfloat162float(h1));
                    __nv_bfloat162 hp; hp.x = h0; hp.y = h1;
                    __nv_bfloat162 lp; lp.x = l0; lp.y = l1;
                    size_t off = (size_t)(r0 + 8 * hh) * ldC + c0;
                    *(__nv_bfloat162*)(Ch + off) = hp;
                    *(__nv_bfloat162*)(Cl + off) = lp;
                }
            }
        }
}

// ---------------- GEMM wrapper kernels -------------------------------------
__global__ void __launch_bounds__(256) k_gemm_proj() {
    const int z = blockIdx.z;
    const size_t a0 = (size_t)blockIdx.y * 128 * FDIM;
    const size_t b0 = (size_t)z * FDIM * DDIM + (size_t)blockIdx.x * 128 * FDIM;
    __nv_bfloat16* Ch = (z == 0) ? g_Q_h : (z == 1) ? g_K_h : g_V_h;
    __nv_bfloat16* Cl = (z == 0) ? g_Q_l : (z == 1) ? g_K_l : g_V_l;
    const size_t c0 = (size_t)blockIdx.y * 128 * DDIM + blockIdx.x * 128;
    gemm_core<1>(g_xpe_h + a0, g_xpe_l + a0, g_Wt_h + b0, g_Wt_l + b0,
                 FDIM, 1.0f, nullptr, DDIM, Ch + c0, Cl + c0);
}

__global__ void __launch_bounds__(256) k_gemm_scores() {
    const size_t b = blockIdx.z;
    const size_t a0 = b * SEQ * DDIM + (size_t)blockIdx.y * 128 * DDIM;
    const size_t b0 = b * SEQ * DDIM + (size_t)blockIdx.x * 128 * DDIM;
    const size_t c0 = b * SEQ * SEQ + (size_t)blockIdx.y * 128 * SEQ + blockIdx.x * 128;
    gemm_core<0>(g_Q_h + a0, g_Q_l + a0, g_K_h + b0, g_K_l + b0,
                 DDIM, 0.04419417382415922f, g_scores + c0, SEQ, nullptr, nullptr);
}

__global__ void __launch_bounds__(256) k_gemm_av(float* __restrict__ out) {
    const size_t b = blockIdx.z;
    const size_t a0 = b * SEQ * SEQ + (size_t)blockIdx.y * 128 * SEQ;
    const size_t b0 = b * DDIM * SEQ + (size_t)blockIdx.x * 128 * SEQ;
    const size_t c0 = b * SEQ * DDIM + (size_t)blockIdx.y * 128 * DDIM + blockIdx.x * 128;
    gemm_core<0>(g_attn_h + a0, g_attn_l + a0, g_Vt_h + b0, g_Vt_l + b0,
                 SEQ, 1.0f, out + c0, DDIM, nullptr, nullptr);
}

// ---------------- aux kernels ----------------------------------------------
__global__ void __launch_bounds__(256) k_addpe_split(const float* __restrict__ x) {
    size_t idx = (size_t)blockIdx.x * 256 + threadIdx.x;
    int f = (int)(idx & (FDIM - 1));
    int s = (int)((idx >> 9) & (SEQ - 1));
    float e     = (float)(f & ~1) * (1.0f / (float)FDIM);
    float denom = powf(10000.0f, e);
    float angle = (float)s / denom;
    double r = fmod((double)angle, 6.283185307179586476925286766559);
    float a = (float)r;
    float pe = (f & 1) ? cosf(a) : sinf(a);
    float v = x[idx] + pe;
    __nv_bfloat16 h = __float2bfloat16(v);
    g_xpe_h[idx] = h;
    g_xpe_l[idx] = __float2bfloat16(v - __bfloat162float(h));
}

// transpose + split W: Wt[z][n][k] = W[z][k][n]
__global__ void __launch_bounds__(256) k_splitW(const float* __restrict__ Wq,
                                                const float* __restrict__ Wk,
                                                const float* __restrict__ Wv) {
    __shared__ float tsm[32][33];
    const int z = blockIdx.z;
    const float* W = (z == 0) ? Wq : (z == 1) ? Wk : Wv;
    const int k0 = blockIdx.y * 32, n0 = blockIdx.x * 32;
    const int tx = threadIdx.x & 31, ty = threadIdx.x >> 5;  // 32 x 8
#pragma unroll
    for (int i = 0; i < 32; i += 8)
        tsm[ty + i][tx] = W[(size_t)(k0 + ty + i) * DDIM + n0 + tx];
    __syncthreads();
#pragma unroll
    for (int i = 0; i < 32; i += 8) {
        float v = tsm[tx][ty + i];
        __nv_bfloat16 h = __float2bfloat16(v);
        size_t off = (size_t)z * FDIM * DDIM + (size_t)(n0 + ty + i) * FDIM + k0 + tx;
        g_Wt_h[off] = h;
        g_Wt_l[off] = __float2bfloat16(v - __bfloat162float(h));
    }
}

// transpose V planes: Vt[b][d][j] = V[b*2048+j][d]
__global__ void __launch_bounds__(256) k_transV() {
    __shared__ __nv_bfloat16 th[32][33];
    __shared__ __nv_bfloat16 tl[32][33];
    const int b = blockIdx.z;
    const int d0 = blockIdx.x * 32, j0 = blockIdx.y * 32;
    const int tx = threadIdx.x & 31, ty = threadIdx.x >> 5;
#pragma unroll
    for (int i = 0; i < 32; i += 8) {
        size_t off = (size_t)(b * SEQ + j0 + ty + i) * DDIM + d0 + tx;
        th[ty + i][tx] = g_V_h[off];
        tl[ty + i][tx] = g_V_l[off];
    }
    __syncthreads();
#pragma unroll
    for (int i = 0; i < 32; i += 8) {
        size_t off = (size_t)b * DDIM * SEQ + (size_t)(d0 + ty + i) * SEQ + j0 + tx;
        g_Vt_h[off] = th[tx][ty + i];
        g_Vt_l[off] = tl[tx][ty + i];
    }
}

// softmax over 2048 cols + split to bf16 planes
__global__ void __launch_bounds__(256) k_softmax_split() {
    const size_t rowoff = (size_t)blockIdx.x * SEQ;
    const float* p = g_scores + rowoff;
    const int tid = threadIdx.x;
    float v[8];
    float m = -1e30f;
#pragma unroll
    for (int i = 0; i < 8; i++) {
        v[i] = p[tid + i * 256];
        m = fmaxf(m, v[i]);
    }
    __shared__ float sh[8];
#pragma unroll
    for (int o = 16; o > 0; o >>= 1)
        m = fmaxf(m, __shfl_xor_sync(0xffffffffu, m, o));
    if ((tid & 31) == 0) sh[tid >> 5] = m;
    __syncthreads();
    m = sh[0];
#pragma unroll
    for (int w = 1; w < 8; w++) m = fmaxf(m, sh[w]);

    float s = 0.0f;
#pragma unroll
    for (int i = 0; i < 8; i++) {
        v[i] = expf(v[i] - m);
        s += v[i];
    }
#pragma unroll
    for (int o = 16; o > 0; o >>= 1)
        s += __shfl_xor_sync(0xffffffffu, s, o);
    __syncthreads();
    if ((tid & 31) == 0) sh[tid >> 5] = s;
    __syncthreads();
    s = 0.0f;
#pragma unroll
    for (int w = 0; w < 8; w++) s += sh[w];
    const float inv = 1.0f / s;
#pragma unroll
    for (int i = 0; i < 8; i++) {
        float a = v[i] * inv;
        __nv_bfloat16 h = __float2bfloat16(a);
        g_attn_h[rowoff + tid + i * 256] = h;
        g_attn_l[rowoff + tid + i * 256] = __float2bfloat16(a - __bfloat162float(h));
    }
}

// ---------------- launch ----------------------------------------------------
// Order: scores is the 4th launch (idx 3) so the fixed ncu capture window
// (-s 5 -c 1, which has landed on launch idx 3 in every passing round)
// profiles a GEMM kernel instead of an aux kernel. Dependencies preserved:
// scores needs only Q/K (proj), transV needs V (proj), av needs transV+softmax.
extern "C" void kernel_launch(void* const* d_in, const int* in_sizes, int n_in,
                              void* d_out, int out_size)
{
    const float* x  = (const float*)d_in[0];
    const float* Wq = (const float*)d_in[1];
    const float* Wk = (const float*)d_in[2];
    const float* Wv = (const float*)d_in[3];
    float* out = (float*)d_out;

    cudaFuncSetAttribute(k_gemm_proj,   cudaFuncAttributeMaxDynamicSharedMemorySize, SMEM_TOTAL);
    cudaFuncSetAttribute(k_gemm_scores, cudaFuncAttributeMaxDynamicSharedMemorySize, SMEM_TOTAL);
    cudaFuncSetAttribute(k_gemm_av,     cudaFuncAttributeMaxDynamicSharedMemorySize, SMEM_TOTAL);

    k_addpe_split<<<((size_t)MTOT * FDIM) / 256, 256>>>(x);                      // 0
    k_splitW<<<dim3(DDIM / 32, FDIM / 32, 3), 256>>>(Wq, Wk, Wv);               // 1
    k_gemm_proj<<<dim3(DDIM / 128, MTOT / 128, 3), 256, SMEM_TOTAL>>>();        // 2
    k_gemm_scores<<<dim3(SEQ / 128, SEQ / 128, BATCH), 256, SMEM_TOTAL>>>();    // 3 <- ncu
    k_transV<<<dim3(DDIM / 32, SEQ / 32, BATCH), 256>>>();                      // 4
    k_softmax_split<<<BATCH * SEQ, 256>>>();                                     // 5
    k_gemm_av<<<dim3(DDIM / 128, SEQ / 128, BATCH), 256, SMEM_TOTAL>>>(out);    // 6
}

// round 13
// speedup vs baseline: 2.5593x; 1.0374x over previous
#include <cuda_runtime.h>
#include <cuda_bf16.h>
#include <math.h>
#include <stdint.h>

#define BATCH 8
#define SEQ   2048
#define FDIM  512
#define DDIM  512
#define MTOT  (BATCH * SEQ)   // 16384

// ---------------- scratch (__device__ globals; no allocs allowed) ----------
__device__ __nv_bfloat16 g_xpe_h[(size_t)MTOT * FDIM];
__device__ __nv_bfloat16 g_xpe_l[(size_t)MTOT * FDIM];
__device__ __nv_bfloat16 g_Wt_h[3 * FDIM * DDIM];      // [z][n][k] (W transposed)
__device__ __nv_bfloat16 g_Wt_l[3 * FDIM * DDIM];
__device__ __nv_bfloat16 g_Q_h[(size_t)MTOT * DDIM];
__device__ __nv_bfloat16 g_Q_l[(size_t)MTOT * DDIM];
__device__ __nv_bfloat16 g_K_h[(size_t)MTOT * DDIM];
__device__ __nv_bfloat16 g_K_l[(size_t)MTOT * DDIM];
__device__ __nv_bfloat16 g_V_h[(size_t)MTOT * DDIM];
__device__ __nv_bfloat16 g_V_l[(size_t)MTOT * DDIM];
__device__ __nv_bfloat16 g_Vt_h[(size_t)MTOT * DDIM];  // [b][d][j]
__device__ __nv_bfloat16 g_Vt_l[(size_t)MTOT * DDIM];
__device__ float         g_scores[(size_t)BATCH * SEQ * SEQ];     // 134MB
__device__ __nv_bfloat16 g_attn_h[(size_t)BATCH * SEQ * SEQ];
__device__ __nv_bfloat16 g_attn_l[(size_t)BATCH * SEQ * SEQ];

// ---------------- PTX helpers ----------------------------------------------
__device__ __forceinline__ uint32_t s2u(const void* p) {
    return (uint32_t)__cvta_generic_to_shared(p);
}
__device__ __forceinline__ void cpa16(uint32_t dst, const void* src) {
    asm volatile("cp.async.cg.shared.global [%0], [%1], 16;\n" :: "r"(dst), "l"(src));
}
#define CP_COMMIT()  asm volatile("cp.async.commit_group;\n" ::: "memory")
#define CP_WAIT1()   asm volatile("cp.async.wait_group 1;\n" ::: "memory")

#define LDM4(r, addr) \
    asm volatile("ldmatrix.sync.aligned.m8n8.x4.shared.b16 {%0,%1,%2,%3}, [%4];" \
                 : "=r"((r)[0]), "=r"((r)[1]), "=r"((r)[2]), "=r"((r)[3]) : "r"(addr))

#define MMA16816(d, a, b0, b1) \
    asm volatile("mma.sync.aligned.m16n8k16.row.col.f32.bf16.bf16.f32 " \
                 "{%0,%1,%2,%3}, {%4,%5,%6,%7}, {%8,%9}, {%0,%1,%2,%3};" \
                 : "+f"((d)[0]), "+f"((d)[1]), "+f"((d)[2]), "+f"((d)[3]) \
                 : "r"((a)[0]), "r"((a)[1]), "r"((a)[2]), "r"((a)[3]), \
                   "r"(b0), "r"(b1))

// ---------------- GEMM: CTA 128x128, K-chunk 32, bf16x3, HMMA --------------
// 2-stage double buffer (80KB) so TWO CTAs fit per SM: cross-CTA overlap fills
// the sync/ldmatrix bubbles that held tensor util at 58% with 1 CTA/SM.
// smem per stage: 4 planes (Ah, Al, Bh, Bl), each 128 rows x 80B (32 bf16 + pad)
#define PLANE_B    10240
#define STAGE_B    40960
#define SMEM_TOTAL (2 * STAGE_B)   // 81920

__device__ __forceinline__ void ld_stage(uint32_t sb,
    const __nv_bfloat16* Ah, const __nv_bfloat16* Al,
    const __nv_bfloat16* Bh, const __nv_bfloat16* Bl,
    int K, int k0, int tid)
{
#pragma unroll
    for (int i = 0; i < 2; i++) {
        int ci = tid + i * 256;
        int r = ci >> 2, c = ci & 3;
        size_t ge = (size_t)r * K + k0 + c * 8;   // bf16 element offset
        uint32_t so = r * 80 + c * 16;
        cpa16(sb + so,               Ah + ge);
        cpa16(sb + PLANE_B + so,     Al + ge);
        cpa16(sb + 2 * PLANE_B + so, Bh + ge);
        cpa16(sb + 3 * PLANE_B + so, Bl + ge);
    }
}

// EPI 0: fp32 C with alpha.  EPI 1: bf16 hi/lo split planes.
template <int EPI>
__device__ __forceinline__ void gemm_core(
    const __nv_bfloat16* __restrict__ Ah, const __nv_bfloat16* __restrict__ Al,
    const __nv_bfloat16* __restrict__ Bh, const __nv_bfloat16* __restrict__ Bl,
    int K, float alpha,
    float* __restrict__ C, int ldC,
    __nv_bfloat16* __restrict__ Ch, __nv_bfloat16* __restrict__ Cl)
{
    extern __shared__ __align__(128) char sm[];
    const uint32_t smb = s2u(sm);
    const int tid = threadIdx.x;
    const int w = tid >> 5, lane = tid & 31;
    const int wr = w & 1, wc = w >> 1;         // warp grid 2 (M) x 4 (N)
    const int q = lane & 7, sel = lane >> 3;   // ldmatrix addressing
    const int g = lane >> 2, t = lane & 3;     // fragment addressing

    // per-thread ldmatrix smem byte offsets (within plane); ks adds ks*32
    uint32_t aoff[4], boff[2];
#pragma unroll
    for (int mt = 0; mt < 4; mt++)
        aoff[mt] = (uint32_t)(wr * 64 + mt * 16 + (sel & 1) * 8 + q) * 80
                 + (uint32_t)(sel >> 1) * 16;
#pragma unroll
    for (int nb = 0; nb < 2; nb++)
        boff[nb] = (uint32_t)(wc * 32 + nb * 16 + (sel >> 1) * 8 + q) * 80
                 + (uint32_t)(sel & 1) * 16;

    const int n = K >> 5;   // K / 32 chunks

    ld_stage(smb, Ah, Al, Bh, Bl, K, 0, tid); CP_COMMIT();

    float acc[4][4][4];
#pragma unroll
    for (int mt = 0; mt < 4; mt++)
#pragma unroll
        for (int nt = 0; nt < 4; nt++)
#pragma unroll
            for (int r = 0; r < 4; r++) acc[mt][nt][r] = 0.0f;

    for (int i = 0; i < n; i++) {
        // prefetch next chunk into the other buffer (freed by the barrier at
        // the end of iteration i-1)
        if (i + 1 < n)
            ld_stage(smb + ((i + 1) & 1) * STAGE_B, Ah, Al, Bh, Bl, K,
                     (i + 1) * 32, tid);
        CP_COMMIT();
        CP_WAIT1();        // stage i resident (<=1 group pending = group i+1)
        __syncthreads();

        const uint32_t sb = smb + (i & 1) * STAGE_B;
#pragma unroll
        for (int ks = 0; ks < 2; ks++) {
            uint32_t ah[4][4], al[4][4], bh[2][4], bl[2][4];
#pragma unroll
            for (int mt = 0; mt < 4; mt++) {
                uint32_t ad = sb + aoff[mt] + ks * 32;
                LDM4(ah[mt], ad);
                LDM4(al[mt], ad + PLANE_B);
            }
#pragma unroll
            for (int nb = 0; nb < 2; nb++) {
                uint32_t bd = sb + 2 * PLANE_B + boff[nb] + ks * 32;
                LDM4(bh[nb], bd);
                LDM4(bl[nb], bd + PLANE_B);
            }
            // term-major issue order keeps dependent MMAs 16 apart
#pragma unroll
            for (int mt = 0; mt < 4; mt++)
#pragma unroll
                for (int nt = 0; nt < 4; nt++) {
                    const uint32_t* B0 = &bh[nt >> 1][(nt & 1) * 2];
                    MMA16816(acc[mt][nt], ah[mt], B0[0], B0[1]);
                }
#pragma unroll
            for (int mt = 0; mt < 4; mt++)
#pragma unroll
                for (int nt = 0; nt < 4; nt++) {
                    const uint32_t* B1 = &bl[nt >> 1][(nt & 1) * 2];
                    MMA16816(acc[mt][nt], ah[mt], B1[0], B1[1]);
                }
#pragma unroll
            for (int mt = 0; mt < 4; mt++)
#pragma unroll
                for (int nt = 0; nt < 4; nt++) {
                    const uint32_t* B0 = &bh[nt >> 1][(nt & 1) * 2];
                    MMA16816(acc[mt][nt], al[mt], B0[0], B0[1]);
                }
        }
        __syncthreads();   // release buffer (i&1) before iter i+1 overwrites it
    }

    // epilogue
#pragma unroll
    for (int mt = 0; mt < 4; mt++)
#pragma unroll
        for (int nt = 0; nt < 4; nt++) {
            int r0 = wr * 64 + mt * 16 + g;
            int c0 = wc * 32 + nt * 8 + 2 * t;
            if (EPI == 0) {
                float2 v0, v1;
                v0.x = alpha * acc[mt][nt][0]; v0.y = alpha * acc[mt][nt][1];
                v1.x = alpha * acc[mt][nt][2]; v1.y = alpha * acc[mt][nt][3];
                *(float2*)(C + (size_t)r0 * ldC + c0)       = v0;
                *(float2*)(C + (size_t)(r0 + 8) * ldC + c0) = v1;
            } else {
#pragma unroll
                for (int hh = 0; hh < 2; hh++) {
                    float v0 = acc[mt][nt][2 * hh + 0];
                    float v1 = acc[mt][nt][2 * hh + 1];
                    __nv_bfloat16 h0 = __float2bfloat16(v0);
                    __nv_bfloat16 h1 = __float2bfloat16(v1);
                    __nv_bfloat16 l0 = __float2bfloat16(v0 - __bfloat162float(h0));
                    __nv_bfloat16 l1 = __float2bfloat16(v1 - __bfloat162float(h1));
                    __nv_bfloat162 hp; hp.x = h0; hp.y = h1;
                    __nv_bfloat162 lp; lp.x = l0; lp.y = l1;
                    size_t off = (size_t)(r0 + 8 * hh) * ldC + c0;
                    *(__nv_bfloat162*)(Ch + off) = hp;
                    *(__nv_bfloat162*)(Cl + off) = lp;
                }
            }
        }
}

// ---------------- GEMM wrapper kernels -------------------------------------
__global__ void __launch_bounds__(256, 2) k_gemm_proj() {
    const int z = blockIdx.z;
    const size_t a0 = (size_t)blockIdx.y * 128 * FDIM;
    const size_t b0 = (size_t)z * FDIM * DDIM + (size_t)blockIdx.x * 128 * FDIM;
    __nv_bfloat16* Ch = (z == 0) ? g_Q_h : (z == 1) ? g_K_h : g_V_h;
    __nv_bfloat16* Cl = (z == 0) ? g_Q_l : (z == 1) ? g_K_l : g_V_l;
    const size_t c0 = (size_t)blockIdx.y * 128 * DDIM + blockIdx.x * 128;
    gemm_core<1>(g_xpe_h + a0, g_xpe_l + a0, g_Wt_h + b0, g_Wt_l + b0,
                 FDIM, 1.0f, nullptr, DDIM, Ch + c0, Cl + c0);
}

__global__ void __launch_bounds__(256, 2) k_gemm_scores() {
    const size_t b = blockIdx.z;
    const size_t a0 = b * SEQ * DDIM + (size_t)blockIdx.y * 128 * DDIM;
    const size_t b0 = b * SEQ * DDIM + (size_t)blockIdx.x * 128 * DDIM;
    const size_t c0 = b * SEQ * SEQ + (size_t)blockIdx.y * 128 * SEQ + blockIdx.x * 128;
    gemm_core<0>(g_Q_h + a0, g_Q_l + a0, g_K_h + b0, g_K_l + b0,
                 DDIM, 0.04419417382415922f, g_scores + c0, SEQ, nullptr, nullptr);
}

__global__ void __launch_bounds__(256, 2) k_gemm_av(float* __restrict__ out) {
    const size_t b = blockIdx.z;
    const size_t a0 = b * SEQ * SEQ + (size_t)blockIdx.y * 128 * SEQ;
    const size_t b0 = b * DDIM * SEQ + (size_t)blockIdx.x * 128 * SEQ;
    const size_t c0 = b * SEQ * DDIM + (size_t)blockIdx.y * 128 * DDIM + blockIdx.x * 128;
    gemm_core<0>(g_attn_h + a0, g_attn_l + a0, g_Vt_h + b0, g_Vt_l + b0,
                 SEQ, 1.0f, out + c0, DDIM, nullptr, nullptr);
}

// ---------------- aux kernels ----------------------------------------------
__global__ void __launch_bounds__(256) k_addpe_split(const float* __restrict__ x) {
    size_t idx = (size_t)blockIdx.x * 256 + threadIdx.x;
    int f = (int)(idx & (FDIM - 1));
    int s = (int)((idx >> 9) & (SEQ - 1));
    float e     = (float)(f & ~1) * (1.0f / (float)FDIM);
    float denom = powf(10000.0f, e);
    float angle = (float)s / denom;
    double r = fmod((double)angle, 6.283185307179586476925286766559);
    float a = (float)r;
    float pe = (f & 1) ? cosf(a) : sinf(a);
    float v = x[idx] + pe;
    __nv_bfloat16 h = __float2bfloat16(v);
    g_xpe_h[idx] = h;
    g_xpe_l[idx] = __float2bfloat16(v - __bfloat162float(h));
}

// transpose + split W: Wt[z][n][k] = W[z][k][n]
__global__ void __launch_bounds__(256) k_splitW(const float* __restrict__ Wq,
                                                const float* __restrict__ Wk,
                                                const float* __restrict__ Wv) {
    __shared__ float tsm[32][33];
    const int z = blockIdx.z;
    const float* W = (z == 0) ? Wq : (z == 1) ? Wk : Wv;
    const int k0 = blockIdx.y * 32, n0 = blockIdx.x * 32;
    const int tx = threadIdx.x & 31, ty = threadIdx.x >> 5;  // 32 x 8
#pragma unroll
    for (int i = 0; i < 32; i += 8)
        tsm[ty + i][tx] = W[(size_t)(k0 + ty + i) * DDIM + n0 + tx];
    __syncthreads();
#pragma unroll
    for (int i = 0; i < 32; i += 8) {
        float v = tsm[tx][ty + i];
        __nv_bfloat16 h = __float2bfloat16(v);
        size_t off = (size_t)z * FDIM * DDIM + (size_t)(n0 + ty + i) * FDIM + k0 + tx;
        g_Wt_h[off] = h;
        g_Wt_l[off] = __float2bfloat16(v - __bfloat162float(h));
    }
}

// transpose V planes: Vt[b][d][j] = V[b*2048+j][d]
__global__ void __launch_bounds__(256) k_transV() {
    __shared__ __nv_bfloat16 th[32][33];
    __shared__ __nv_bfloat16 tl[32][33];
    const int b = blockIdx.z;
    const int d0 = blockIdx.x * 32, j0 = blockIdx.y * 32;
    const int tx = threadIdx.x & 31, ty = threadIdx.x >> 5;
#pragma unroll
    for (int i = 0; i < 32; i += 8) {
        size_t off = (size_t)(b * SEQ + j0 + ty + i) * DDIM + d0 + tx;
        th[ty + i][tx] = g_V_h[off];
        tl[ty + i][tx] = g_V_l[off];
    }
    __syncthreads();
#pragma unroll
    for (int i = 0; i < 32; i += 8) {
        size_t off = (size_t)b * DDIM * SEQ + (size_t)(d0 + ty + i) * SEQ + j0 + tx;
        g_Vt_h[off] = th[tx][ty + i];
        g_Vt_l[off] = tl[tx][ty + i];
    }
}

// softmax over 2048 cols + split to bf16 planes
__global__ void __launch_bounds__(256) k_softmax_split() {
    const size_t rowoff = (size_t)blockIdx.x * SEQ;
    const float* p = g_scores + rowoff;
    const int tid = threadIdx.x;
    float v[8];
    float m = -1e30f;
#pragma unroll
    for (int i = 0; i < 8; i++) {
        v[i] = p[tid + i * 256];
        m = fmaxf(m, v[i]);
    }
    __shared__ float sh[8];
#pragma unroll
    for (int o = 16; o > 0; o >>= 1)
        m = fmaxf(m, __shfl_xor_sync(0xffffffffu, m, o));
    if ((tid & 31) == 0) sh[tid >> 5] = m;
    __syncthreads();
    m = sh[0];
#pragma unroll
    for (int w = 1; w < 8; w++) m = fmaxf(m, sh[w]);

    float s = 0.0f;
#pragma unroll
    for (int i = 0; i < 8; i++) {
        v[i] = expf(v[i] - m);
        s += v[i];
    }
#pragma unroll
    for (int o = 16; o > 0; o >>= 1)
        s += __shfl_xor_sync(0xffffffffu, s, o);
    __syncthreads();
    if ((tid & 31) == 0) sh[tid >> 5] = s;
    __syncthreads();
    s = 0.0f;
#pragma unroll
    for (int w = 0; w < 8; w++) s += sh[w];
    const float inv = 1.0f / s;
#pragma unroll
    for (int i = 0; i < 8; i++) {
        float a = v[i] * inv;
        __nv_bfloat16 h = __float2bfloat16(a);
        g_attn_h[rowoff + tid + i * 256] = h;
        g_attn_l[rowoff + tid + i * 256] = __float2bfloat16(a - __bfloat162float(h));
    }
}

// ---------------- launch ----------------------------------------------------
// scores stays at launch idx 3 so the fixed ncu window keeps profiling it.
extern "C" void kernel_launch(void* const* d_in, const int* in_sizes, int n_in,
                              void* d_out, int out_size)
{
    const float* x  = (const float*)d_in[0];
    const float* Wq = (const float*)d_in[1];
    const float* Wk = (const float*)d_in[2];
    const float* Wv = (const float*)d_in[3];
    float* out = (float*)d_out;

    cudaFuncSetAttribute(k_gemm_proj,   cudaFuncAttributeMaxDynamicSharedMemorySize, SMEM_TOTAL);
    cudaFuncSetAttribute(k_gemm_scores, cudaFuncAttributeMaxDynamicSharedMemorySize, SMEM_TOTAL);
    cudaFuncSetAttribute(k_gemm_av,     cudaFuncAttributeMaxDynamicSharedMemorySize, SMEM_TOTAL);

    k_addpe_split<<<((size_t)MTOT * FDIM) / 256, 256>>>(x);                      // 0
    k_splitW<<<dim3(DDIM / 32, FDIM / 32, 3), 256>>>(Wq, Wk, Wv);               // 1
    k_gemm_proj<<<dim3(DDIM / 128, MTOT / 128, 3), 256, SMEM_TOTAL>>>();        // 2
    k_gemm_scores<<<dim3(SEQ / 128, SEQ / 128, BATCH), 256, SMEM_TOTAL>>>();    // 3 <- ncu
    k_transV<<<dim3(DDIM / 32, SEQ / 32, BATCH), 256>>>();                      // 4
    k_softmax_split<<<BATCH * SEQ, 256>>>();                                     // 5
    k_gemm_av<<<dim3(DDIM / 128, SEQ / 128, BATCH), 256, SMEM_TOTAL>>>(out);    // 6
}

// round 14
// speedup vs baseline: 3.5181x; 1.3746x over previous
#include <cuda_runtime.h>
#include <cuda_fp16.h>
#include <math.h>
#include <stdint.h>

#define BATCH 8
#define SEQ   2048
#define FDIM  512
#define DDIM  512
#define MTOT  (BATCH * SEQ)   // 16384

// ---------------- scratch (__device__ globals; no allocs allowed) ----------
// A-side operands carry hi+lo fp16 planes (2^-22 combined); B-side consumers
// read only the hi plane (single rounded fp16, 2^-11 — the budgeted error).
__device__ __half g_xpe_h[(size_t)MTOT * FDIM];
__device__ __half g_xpe_l[(size_t)MTOT * FDIM];
__device__ __half g_Wt_h[3 * FDIM * DDIM];      // [z][n][k] (W transposed, single plane)
__device__ __half g_Q_h[(size_t)MTOT * DDIM];
__device__ __half g_Q_l[(size_t)MTOT * DDIM];
__device__ __half g_K_h[(size_t)MTOT * DDIM];   // only hi used (B side of scores)
__device__ __half g_K_l[(size_t)MTOT * DDIM];
__device__ __half g_V_h[(size_t)MTOT * DDIM];
__device__ __half g_V_l[(size_t)MTOT * DDIM];
__device__ __half g_Vt_h[(size_t)MTOT * DDIM];  // [b][d][j] (single plane)
__device__ float  g_scores[(size_t)BATCH * SEQ * SEQ];     // 134MB
__device__ __half g_attn_h[(size_t)BATCH * SEQ * SEQ];
__device__ __half g_attn_l[(size_t)BATCH * SEQ * SEQ];

// ---------------- PTX helpers ----------------------------------------------
__device__ __forceinline__ uint32_t s2u(const void* p) {
    return (uint32_t)__cvta_generic_to_shared(p);
}
__device__ __forceinline__ void cpa16(uint32_t dst, const void* src) {
    asm volatile("cp.async.cg.shared.global [%0], [%1], 16;\n" :: "r"(dst), "l"(src));
}
#define CP_COMMIT()  asm volatile("cp.async.commit_group;\n" ::: "memory")
#define CP_WAIT1()   asm volatile("cp.async.wait_group 1;\n" ::: "memory")

#define LDM4(r, addr) \
    asm volatile("ldmatrix.sync.aligned.m8n8.x4.shared.b16 {%0,%1,%2,%3}, [%4];" \
                 : "=r"((r)[0]), "=r"((r)[1]), "=r"((r)[2]), "=r"((r)[3]) : "r"(addr))

#define MMA16816(d, a, b0, b1) \
    asm volatile("mma.sync.aligned.m16n8k16.row.col.f32.f16.f16.f32 " \
                 "{%0,%1,%2,%3}, {%4,%5,%6,%7}, {%8,%9}, {%0,%1,%2,%3};" \
                 : "+f"((d)[0]), "+f"((d)[1]), "+f"((d)[2]), "+f"((d)[3]) \
                 : "r"((a)[0]), "r"((a)[1]), "r"((a)[2]), "r"((a)[3]), \
                   "r"(b0), "r"(b1))

__device__ __forceinline__ void h_split(float v, __half* h, __half* l) {
    __half hh = __float2half(v);
    *h = hh;
    *l = __float2half(v - __half2float(hh));
}

// ---------------- GEMM: CTA 128x128, K-chunk 32, fp16 2-term, HMMA ---------
// smem per stage: 3 planes (Ah, Al, Bh), each 128 rows x 80B (32 fp16 + pad)
#define PLANE_B    10240
#define STAGE_B    30720
#define SMEM_TOTAL (2 * STAGE_B)   // 61440 -> 2 CTAs/SM

__device__ __forceinline__ void ld_stage(uint32_t sb,
    const __half* Ah, const __half* Al, const __half* Bh,
    int K, int k0, int tid)
{
#pragma unroll
    for (int i = 0; i < 2; i++) {
        int ci = tid + i * 256;
        int r = ci >> 2, c = ci & 3;
        size_t ge = (size_t)r * K + k0 + c * 8;   // fp16 element offset
        uint32_t so = r * 80 + c * 16;
        cpa16(sb + so,               Ah + ge);
        cpa16(sb + PLANE_B + so,     Al + ge);
        cpa16(sb + 2 * PLANE_B + so, Bh + ge);
    }
}

// EPI 0: fp32 C with alpha.  EPI 1: fp16 hi/lo split planes.
template <int EPI>
__device__ __forceinline__ void gemm_core(
    const __half* __restrict__ Ah, const __half* __restrict__ Al,
    const __half* __restrict__ Bh,
    int K, float alpha,
    float* __restrict__ C, int ldC,
    __half* __restrict__ Ch, __half* __restrict__ Cl)
{
    extern __shared__ __align__(128) char sm[];
    const uint32_t smb = s2u(sm);
    const int tid = threadIdx.x;
    const int w = tid >> 5, lane = tid & 31;
    const int wr = w & 1, wc = w >> 1;         // warp grid 2 (M) x 4 (N)
    const int q = lane & 7, sel = lane >> 3;   // ldmatrix addressing
    const int g = lane >> 2, t = lane & 3;     // fragment addressing

    uint32_t aoff[4], boff[2];
#pragma unroll
    for (int mt = 0; mt < 4; mt++)
        aoff[mt] = (uint32_t)(wr * 64 + mt * 16 + (sel & 1) * 8 + q) * 80
                 + (uint32_t)(sel >> 1) * 16;
#pragma unroll
    for (int nb = 0; nb < 2; nb++)
        boff[nb] = (uint32_t)(wc * 32 + nb * 16 + (sel >> 1) * 8 + q) * 80
                 + (uint32_t)(sel & 1) * 16;

    const int n = K >> 5;   // K / 32 chunks

    ld_stage(smb, Ah, Al, Bh, K, 0, tid); CP_COMMIT();

    float acc[4][4][4];
#pragma unroll
    for (int mt = 0; mt < 4; mt++)
#pragma unroll
        for (int nt = 0; nt < 4; nt++)
#pragma unroll
            for (int r = 0; r < 4; r++) acc[mt][nt][r] = 0.0f;

    for (int i = 0; i < n; i++) {
        if (i + 1 < n)
            ld_stage(smb + ((i + 1) & 1) * STAGE_B, Ah, Al, Bh, K,
                     (i + 1) * 32, tid);
        CP_COMMIT();
        CP_WAIT1();        // stage i resident
        __syncthreads();

        const uint32_t sb = smb + (i & 1) * STAGE_B;
#pragma unroll
        for (int ks = 0; ks < 2; ks++) {
            uint32_t ah[4][4], al[4][4], bh[2][4];
#pragma unroll
            for (int mt = 0; mt < 4; mt++) {
                uint32_t ad = sb + aoff[mt] + ks * 32;
                LDM4(ah[mt], ad);
                LDM4(al[mt], ad + PLANE_B);
            }
#pragma unroll
            for (int nb = 0; nb < 2; nb++)
                LDM4(bh[nb], sb + 2 * PLANE_B + boff[nb] + ks * 32);
            // term-major: dependent MMAs 16 apart
#pragma unroll
            for (int mt = 0; mt < 4; mt++)
#pragma unroll
                for (int nt = 0; nt < 4; nt++) {
                    const uint32_t* B0 = &bh[nt >> 1][(nt & 1) * 2];
                    MMA16816(acc[mt][nt], ah[mt], B0[0], B0[1]);
                }
#pragma unroll
            for (int mt = 0; mt < 4; mt++)
#pragma unroll
                for (int nt = 0; nt < 4; nt++) {
                    const uint32_t* B0 = &bh[nt >> 1][(nt & 1) * 2];
                    MMA16816(acc[mt][nt], al[mt], B0[0], B0[1]);
                }
        }
        __syncthreads();   // release buffer (i&1)
    }

    // epilogue
#pragma unroll
    for (int mt = 0; mt < 4; mt++)
#pragma unroll
        for (int nt = 0; nt < 4; nt++) {
            int r0 = wr * 64 + mt * 16 + g;
            int c0 = wc * 32 + nt * 8 + 2 * t;
            if (EPI == 0) {
                float2 v0, v1;
                v0.x = alpha * acc[mt][nt][0]; v0.y = alpha * acc[mt][nt][1];
                v1.x = alpha * acc[mt][nt][2]; v1.y = alpha * acc[mt][nt][3];
                *(float2*)(C + (size_t)r0 * ldC + c0)       = v0;
                *(float2*)(C + (size_t)(r0 + 8) * ldC + c0) = v1;
            } else {
#pragma unroll
                for (int hh2 = 0; hh2 < 2; hh2++) {
                    float v0 = acc[mt][nt][2 * hh2 + 0];
                    float v1 = acc[mt][nt][2 * hh2 + 1];
                    __half h0, l0, h1, l1;
                    h_split(v0, &h0, &l0);
                    h_split(v1, &h1, &l1);
                    __half2 hp; hp.x = h0; hp.y = h1;
                    __half2 lp; lp.x = l0; lp.y = l1;
                    size_t off = (size_t)(r0 + 8 * hh2) * ldC + c0;
                    *(__half2*)(Ch + off) = hp;
                    *(__half2*)(Cl + off) = lp;
                }
            }
        }
}

// ---------------- GEMM wrapper kernels -------------------------------------
__global__ void __launch_bounds__(256, 2) k_gemm_proj() {
    const int z = blockIdx.z;
    const size_t a0 = (size_t)blockIdx.y * 128 * FDIM;
    const size_t b0 = (size_t)z * FDIM * DDIM + (size_t)blockIdx.x * 128 * FDIM;
    __half* Ch = (z == 0) ? g_Q_h : (z == 1) ? g_K_h : g_V_h;
    __half* Cl = (z == 0) ? g_Q_l : (z == 1) ? g_K_l : g_V_l;
    const size_t c0 = (size_t)blockIdx.y * 128 * DDIM + blockIdx.x * 128;
    gemm_core<1>(g_xpe_h + a0, g_xpe_l + a0, g_Wt_h + b0,
                 FDIM, 1.0f, nullptr, DDIM, Ch + c0, Cl + c0);
}

__global__ void __launch_bounds__(256, 2) k_gemm_scores() {
    const size_t b = blockIdx.z;
    const size_t a0 = b * SEQ * DDIM + (size_t)blockIdx.y * 128 * DDIM;
    const size_t b0 = b * SEQ * DDIM + (size_t)blockIdx.x * 128 * DDIM;
    const size_t c0 = b * SEQ * SEQ + (size_t)blockIdx.y * 128 * SEQ + blockIdx.x * 128;
    gemm_core<0>(g_Q_h + a0, g_Q_l + a0, g_K_h + b0,
                 DDIM, 0.04419417382415922f, g_scores + c0, SEQ, nullptr, nullptr);
}

__global__ void __launch_bounds__(256, 2) k_gemm_av(float* __restrict__ out) {
    const size_t b = blockIdx.z;
    const size_t a0 = b * SEQ * SEQ + (size_t)blockIdx.y * 128 * SEQ;
    const size_t b0 = b * DDIM * SEQ + (size_t)blockIdx.x * 128 * SEQ;
    const size_t c0 = b * SEQ * DDIM + (size_t)blockIdx.y * 128 * DDIM + blockIdx.x * 128;
    gemm_core<0>(g_attn_h + a0, g_attn_l + a0, g_Vt_h + b0,
                 SEQ, 1.0f, out + c0, DDIM, nullptr, nullptr);
}

// ---------------- aux kernels ----------------------------------------------
__global__ void __launch_bounds__(256) k_addpe_split(const float* __restrict__ x) {
    size_t idx = (size_t)blockIdx.x * 256 + threadIdx.x;
    int f = (int)(idx & (FDIM - 1));
    int s = (int)((idx >> 9) & (SEQ - 1));
    float e     = (float)(f & ~1) * (1.0f / (float)FDIM);
    float denom = powf(10000.0f, e);
    float angle = (float)s / denom;
    double r = fmod((double)angle, 6.283185307179586476925286766559);
    float a = (float)r;
    float pe = (f & 1) ? cosf(a) : sinf(a);
    float v = x[idx] + pe;
    __half h, l;
    h_split(v, &h, &l);
    g_xpe_h[idx] = h;
    g_xpe_l[idx] = l;
}

// transpose W: Wt[z][n][k] = W[z][k][n] (single fp16 plane)
__global__ void __launch_bounds__(256) k_splitW(const float* __restrict__ Wq,
                                                const float* __restrict__ Wk,
                                                const float* __restrict__ Wv) {
    __shared__ float tsm[32][33];
    const int z = blockIdx.z;
    const float* W = (z == 0) ? Wq : (z == 1) ? Wk : Wv;
    const int k0 = blockIdx.y * 32, n0 = blockIdx.x * 32;
    const int tx = threadIdx.x & 31, ty = threadIdx.x >> 5;  // 32 x 8
#pragma unroll
    for (int i = 0; i < 32; i += 8)
        tsm[ty + i][tx] = W[(size_t)(k0 + ty + i) * DDIM + n0 + tx];
    __syncthreads();
#pragma unroll
    for (int i = 0; i < 32; i += 8) {
        size_t off = (size_t)z * FDIM * DDIM + (size_t)(n0 + ty + i) * FDIM + k0 + tx;
        g_Wt_h[off] = __float2half(tsm[tx][ty + i]);
    }
}

// transpose V hi plane: Vt[b][d][j] = V_h[b*2048+j][d]
__global__ void __launch_bounds__(256) k_transV() {
    __shared__ __half th[32][33];
    const int b = blockIdx.z;
    const int d0 = blockIdx.x * 32, j0 = blockIdx.y * 32;
    const int tx = threadIdx.x & 31, ty = threadIdx.x >> 5;
#pragma unroll
    for (int i = 0; i < 32; i += 8) {
        size_t off = (size_t)(b * SEQ + j0 + ty + i) * DDIM + d0 + tx;
        th[ty + i][tx] = g_V_h[off];
    }
    __syncthreads();
#pragma unroll
    for (int i = 0; i < 32; i += 8) {
        size_t off = (size_t)b * DDIM * SEQ + (size_t)(d0 + ty + i) * SEQ + j0 + tx;
        g_Vt_h[off] = th[tx][ty + i];
    }
}

// softmax over 2048 cols + fp16 split planes
__global__ void __launch_bounds__(256) k_softmax_split() {
    const size_t rowoff = (size_t)blockIdx.x * SEQ;
    const float* p = g_scores + rowoff;
    const int tid = threadIdx.x;
    float v[8];
    float m = -1e30f;
#pragma unroll
    for (int i = 0; i < 8; i++) {
        v[i] = p[tid + i * 256];
        m = fmaxf(m, v[i]);
    }
    __shared__ float sh[8];
#pragma unroll
    for (int o = 16; o > 0; o >>= 1)
        m = fmaxf(m, __shfl_xor_sync(0xffffffffu, m, o));
    if ((tid & 31) == 0) sh[tid >> 5] = m;
    __syncthreads();
    m = sh[0];
#pragma unroll
    for (int w = 1; w < 8; w++) m = fmaxf(m, sh[w]);

    float s = 0.0f;
#pragma unroll
    for (int i = 0; i < 8; i++) {
        v[i] = expf(v[i] - m);
        s += v[i];
    }
#pragma unroll
    for (int o = 16; o > 0; o >>= 1)
        s += __shfl_xor_sync(0xffffffffu, s, o);
    __syncthreads();
    if ((tid & 31) == 0) sh[tid >> 5] = s;
    __syncthreads();
    s = 0.0f;
#pragma unroll
    for (int w = 0; w < 8; w++) s += sh[w];
    const float inv = 1.0f / s;
#pragma unroll
    for (int i = 0; i < 8; i++) {
        float a = v[i] * inv;
        __half h, l;
        h_split(a, &h, &l);
        g_attn_h[rowoff + tid + i * 256] = h;
        g_attn_l[rowoff + tid + i * 256] = l;
    }
}

// ---------------- launch ----------------------------------------------------
// scores stays at launch idx 3 so the fixed ncu window keeps profiling it.
extern "C" void kernel_launch(void* const* d_in, const int* in_sizes, int n_in,
                              void* d_out, int out_size)
{
    const float* x  = (const float*)d_in[0];
    const float* Wq = (const float*)d_in[1];
    const float* Wk = (const float*)d_in[2];
    const float* Wv = (const float*)d_in[3];
    float* out = (float*)d_out;

    cudaFuncSetAttribute(k_gemm_proj,   cudaFuncAttributeMaxDynamicSharedMemorySize, SMEM_TOTAL);
    cudaFuncSetAttribute(k_gemm_scores, cudaFuncAttributeMaxDynamicSharedMemorySize, SMEM_TOTAL);
    cudaFuncSetAttribute(k_gemm_av,     cudaFuncAttributeMaxDynamicSharedMemorySize, SMEM_TOTAL);

    k_addpe_split<<<((size_t)MTOT * FDIM) / 256, 256>>>(x);                      // 0
    k_splitW<<<dim3(DDIM / 32, FDIM / 32, 3), 256>>>(Wq, Wk, Wv);               // 1
    k_gemm_proj<<<dim3(DDIM / 128, MTOT / 128, 3), 256, SMEM_TOTAL>>>();        // 2
    k_gemm_scores<<<dim3(SEQ / 128, SEQ / 128, BATCH), 256, SMEM_TOTAL>>>();    // 3 <- ncu
    k_transV<<<dim3(DDIM / 32, SEQ / 32, BATCH), 256>>>();                      // 4
    k_softmax_split<<<BATCH * SEQ, 256>>>();                                     // 5
    k_gemm_av<<<dim3(DDIM / 128, SEQ / 128, BATCH), 256, SMEM_TOTAL>>>(out);    // 6
}

// round 15
// speedup vs baseline: 5.3558x; 1.5224x over previous
#include <cuda_runtime.h>
#include <cuda_fp16.h>
#include <math.h>
#include <stdint.h>

#define BATCH 8
#define SEQ   2048
#define FDIM  512
#define DDIM  512
#define MTOT  (BATCH * SEQ)   // 16384

// ---------------- scratch (__device__ globals; no allocs allowed) ----------
// 1-term fp16 everywhere: every GEMM operand is a single rounded fp16 plane.
// Error budget: ~6 independent 2^-11 roundings -> ~4e-4 aggregate (measured
// 2.5e-4 with only the 3 B-side roundings; quadrature scaling).
__device__ __half g_xpe[(size_t)MTOT * FDIM];
__device__ __half g_Wt[3 * FDIM * DDIM];      // [z][n][k] (W transposed)
__device__ __half g_Q[(size_t)MTOT * DDIM];
__device__ __half g_K[(size_t)MTOT * DDIM];
__device__ __half g_V[(size_t)MTOT * DDIM];
__device__ __half g_Vt[(size_t)MTOT * DDIM];  // [b][d][j]
__device__ float  g_scores[(size_t)BATCH * SEQ * SEQ];     // 134MB
__device__ __half g_attn[(size_t)BATCH * SEQ * SEQ];

// ---------------- PTX helpers ----------------------------------------------
__device__ __forceinline__ uint32_t s2u(const void* p) {
    return (uint32_t)__cvta_generic_to_shared(p);
}
__device__ __forceinline__ void cpa16(uint32_t dst, const void* src) {
    asm volatile("cp.async.cg.shared.global [%0], [%1], 16;\n" :: "r"(dst), "l"(src));
}
#define CP_COMMIT()  asm volatile("cp.async.commit_group;\n" ::: "memory")
#define CP_WAIT1()   asm volatile("cp.async.wait_group 1;\n" ::: "memory")

#define LDM4(r, addr) \
    asm volatile("ldmatrix.sync.aligned.m8n8.x4.shared.b16 {%0,%1,%2,%3}, [%4];" \
                 : "=r"((r)[0]), "=r"((r)[1]), "=r"((r)[2]), "=r"((r)[3]) : "r"(addr))

#define MMA16816(d, a, b0, b1) \
    asm volatile("mma.sync.aligned.m16n8k16.row.col.f32.f16.f16.f32 " \
                 "{%0,%1,%2,%3}, {%4,%5,%6,%7}, {%8,%9}, {%0,%1,%2,%3};" \
                 : "+f"((d)[0]), "+f"((d)[1]), "+f"((d)[2]), "+f"((d)[3]) \
                 : "r"((a)[0]), "r"((a)[1]), "r"((a)[2]), "r"((a)[3]), \
                   "r"(b0), "r"(b1))

// ---------------- GEMM: CTA 128x128, K-chunk 32, fp16 1-term, HMMA ---------
// smem per stage: 2 planes (A, B), each 128 rows x 80B (32 fp16 + pad)
#define PLANE_B    10240
#define STAGE_B    20480
#define SMEM_TOTAL (2 * STAGE_B)   // 40960 -> 2 CTAs/SM

__device__ __forceinline__ void ld_stage(uint32_t sb,
    const __half* A, const __half* B,
    int K, int k0, int tid)
{
#pragma unroll
    for (int i = 0; i < 2; i++) {
        int ci = tid + i * 256;
        int r = ci >> 2, c = ci & 3;
        size_t ge = (size_t)r * K + k0 + c * 8;   // fp16 element offset
        uint32_t so = r * 80 + c * 16;
        cpa16(sb + so,           A + ge);
        cpa16(sb + PLANE_B + so, B + ge);
    }
}

// EPI 0: fp32 C with alpha.  EPI 1: fp16 plane.
template <int EPI>
__device__ __forceinline__ void gemm_core(
    const __half* __restrict__ A, const __half* __restrict__ B,
    int K, float alpha,
    float* __restrict__ C, int ldC,
    __half* __restrict__ Ch)
{
    extern __shared__ __align__(128) char sm[];
    const uint32_t smb = s2u(sm);
    const int tid = threadIdx.x;
    const int w = tid >> 5, lane = tid & 31;
    const int wr = w & 1, wc = w >> 1;         // warp grid 2 (M) x 4 (N)
    const int q = lane & 7, sel = lane >> 3;   // ldmatrix addressing
    const int g = lane >> 2, t = lane & 3;     // fragment addressing

    uint32_t aoff[4], boff[2];
#pragma unroll
    for (int mt = 0; mt < 4; mt++)
        aoff[mt] = (uint32_t)(wr * 64 + mt * 16 + (sel & 1) * 8 + q) * 80
                 + (uint32_t)(sel >> 1) * 16;
#pragma unroll
    for (int nb = 0; nb < 2; nb++)
        boff[nb] = (uint32_t)(wc * 32 + nb * 16 + (sel >> 1) * 8 + q) * 80
                 + (uint32_t)(sel & 1) * 16;

    const int n = K >> 5;   // K / 32 chunks

    ld_stage(smb, A, B, K, 0, tid); CP_COMMIT();

    float acc[4][4][4];
#pragma unroll
    for (int mt = 0; mt < 4; mt++)
#pragma unroll
        for (int nt = 0; nt < 4; nt++)
#pragma unroll
            for (int r = 0; r < 4; r++) acc[mt][nt][r] = 0.0f;

    for (int i = 0; i < n; i++) {
        if (i + 1 < n)
            ld_stage(smb + ((i + 1) & 1) * STAGE_B, A, B, K, (i + 1) * 32, tid);
        CP_COMMIT();
        CP_WAIT1();        // stage i resident
        __syncthreads();

        const uint32_t sb = smb + (i & 1) * STAGE_B;
#pragma unroll
        for (int ks = 0; ks < 2; ks++) {
            uint32_t ah[4][4], bh[2][4];
#pragma unroll
            for (int mt = 0; mt < 4; mt++)
                LDM4(ah[mt], sb + aoff[mt] + ks * 32);
#pragma unroll
            for (int nb = 0; nb < 2; nb++)
                LDM4(bh[nb], sb + PLANE_B + boff[nb] + ks * 32);
#pragma unroll
            for (int mt = 0; mt < 4; mt++)
#pragma unroll
                for (int nt = 0; nt < 4; nt++) {
                    const uint32_t* B0 = &bh[nt >> 1][(nt & 1) * 2];
                    MMA16816(acc[mt][nt], ah[mt], B0[0], B0[1]);
                }
        }
        __syncthreads();   // release buffer (i&1)
    }

    // epilogue
#pragma unroll
    for (int mt = 0; mt < 4; mt++)
#pragma unroll
        for (int nt = 0; nt < 4; nt++) {
            int r0 = wr * 64 + mt * 16 + g;
            int c0 = wc * 32 + nt * 8 + 2 * t;
            if (EPI == 0) {
                float2 v0, v1;
                v0.x = alpha * acc[mt][nt][0]; v0.y = alpha * acc[mt][nt][1];
                v1.x = alpha * acc[mt][nt][2]; v1.y = alpha * acc[mt][nt][3];
                *(float2*)(C + (size_t)r0 * ldC + c0)       = v0;
                *(float2*)(C + (size_t)(r0 + 8) * ldC + c0) = v1;
            } else {
#pragma unroll
                for (int hh = 0; hh < 2; hh++) {
                    __half2 hp;
                    hp.x = __float2half(acc[mt][nt][2 * hh + 0]);
                    hp.y = __float2half(acc[mt][nt][2 * hh + 1]);
                    *(__half2*)(Ch + (size_t)(r0 + 8 * hh) * ldC + c0) = hp;
                }
            }
        }
}

// ---------------- GEMM wrapper kernels -------------------------------------
__global__ void __launch_bounds__(256, 2) k_gemm_proj() {
    const int z = blockIdx.z;
    const size_t a0 = (size_t)blockIdx.y * 128 * FDIM;
    const size_t b0 = (size_t)z * FDIM * DDIM + (size_t)blockIdx.x * 128 * FDIM;
    __half* Cz = (z == 0) ? g_Q : (z == 1) ? g_K : g_V;
    const size_t c0 = (size_t)blockIdx.y * 128 * DDIM + blockIdx.x * 128;
    gemm_core<1>(g_xpe + a0, g_Wt + b0, FDIM, 1.0f, nullptr, DDIM, Cz + c0);
}

__global__ void __launch_bounds__(256, 2) k_gemm_scores() {
    const size_t b = blockIdx.z;
    const size_t a0 = b * SEQ * DDIM + (size_t)blockIdx.y * 128 * DDIM;
    const size_t b0 = b * SEQ * DDIM + (size_t)blockIdx.x * 128 * DDIM;
    const size_t c0 = b * SEQ * SEQ + (size_t)blockIdx.y * 128 * SEQ + blockIdx.x * 128;
    gemm_core<0>(g_Q + a0, g_K + b0,
                 DDIM, 0.04419417382415922f, g_scores + c0, SEQ, nullptr);
}

__global__ void __launch_bounds__(256, 2) k_gemm_av(float* __restrict__ out) {
    const size_t b = blockIdx.z;
    const size_t a0 = b * SEQ * SEQ + (size_t)blockIdx.y * 128 * SEQ;
    const size_t b0 = b * DDIM * SEQ + (size_t)blockIdx.x * 128 * SEQ;
    const size_t c0 = b * SEQ * DDIM + (size_t)blockIdx.y * 128 * DDIM + blockIdx.x * 128;
    gemm_core<0>(g_attn + a0, g_Vt + b0, SEQ, 1.0f, out + c0, DDIM, nullptr);
}

// ---------------- aux kernels ----------------------------------------------
__global__ void __launch_bounds__(256) k_addpe(const float* __restrict__ x) {
    size_t idx = (size_t)blockIdx.x * 256 + threadIdx.x;
    int f = (int)(idx & (FDIM - 1));
    int s = (int)((idx >> 9) & (SEQ - 1));
    float e     = (float)(f & ~1) * (1.0f / (float)FDIM);
    float denom = powf(10000.0f, e);
    float angle = (float)s / denom;
    double r = fmod((double)angle, 6.283185307179586476925286766559);
    float a = (float)r;
    float pe = (f & 1) ? cosf(a) : sinf(a);
    g_xpe[idx] = __float2half(x[idx] + pe);
}

// transpose W: Wt[z][n][k] = W[z][k][n]
__global__ void __launch_bounds__(256) k_transW(const float* __restrict__ Wq,
                                                const float* __restrict__ Wk,
                                                const float* __restrict__ Wv) {
    __shared__ float tsm[32][33];
    const int z = blockIdx.z;
    const float* W = (z == 0) ? Wq : (z == 1) ? Wk : Wv;
    const int k0 = blockIdx.y * 32, n0 = blockIdx.x * 32;
    const int tx = threadIdx.x & 31, ty = threadIdx.x >> 5;  // 32 x 8
#pragma unroll
    for (int i = 0; i < 32; i += 8)
        tsm[ty + i][tx] = W[(size_t)(k0 + ty + i) * DDIM + n0 + tx];
    __syncthreads();
#pragma unroll
    for (int i = 0; i < 32; i += 8) {
        size_t off = (size_t)z * FDIM * DDIM + (size_t)(n0 + ty + i) * FDIM + k0 + tx;
        g_Wt[off] = __float2half(tsm[tx][ty + i]);
    }
}

// transpose V: Vt[b][d][j] = V[b*2048+j][d]
__global__ void __launch_bounds__(256) k_transV() {
    __shared__ __half th[32][33];
    const int b = blockIdx.z;
    const int d0 = blockIdx.x * 32, j0 = blockIdx.y * 32;
    const int tx = threadIdx.x & 31, ty = threadIdx.x >> 5;
#pragma unroll
    for (int i = 0; i < 32; i += 8) {
        size_t off = (size_t)(b * SEQ + j0 + ty + i) * DDIM + d0 + tx;
        th[ty + i][tx] = g_V[off];
    }
    __syncthreads();
#pragma unroll
    for (int i = 0; i < 32; i += 8) {
        size_t off = (size_t)b * DDIM * SEQ + (size_t)(d0 + ty + i) * SEQ + j0 + tx;
        g_Vt[off] = th[tx][ty + i];
    }
}

// softmax over 2048 cols -> fp16 attn
__global__ void __launch_bounds__(256) k_softmax() {
    const size_t rowoff = (size_t)blockIdx.x * SEQ;
    const float* p = g_scores + rowoff;
    const int tid = threadIdx.x;
    float v[8];
    float m = -1e30f;
#pragma unroll
    for (int i = 0; i < 8; i++) {
        v[i] = p[tid + i * 256];
        m = fmaxf(m, v[i]);
    }
    __shared__ float sh[8];
#pragma unroll
    for (int o = 16; o > 0; o >>= 1)
        m = fmaxf(m, __shfl_xor_sync(0xffffffffu, m, o));
    if ((tid & 31) == 0) sh[tid >> 5] = m;
    __syncthreads();
    m = sh[0];
#pragma unroll
    for (int w = 1; w < 8; w++) m = fmaxf(m, sh[w]);

    float s = 0.0f;
#pragma unroll
    for (int i = 0; i < 8; i++) {
        v[i] = expf(v[i] - m);
        s += v[i];
    }
#pragma unroll
    for (int o = 16; o > 0; o >>= 1)
        s += __shfl_xor_sync(0xffffffffu, s, o);
    __syncthreads();
    if ((tid & 31) == 0) sh[tid >> 5] = s;
    __syncthreads();
    s = 0.0f;
#pragma unroll
    for (int w = 0; w < 8; w++) s += sh[w];
    const float inv = 1.0f / s;
#pragma unroll
    for (int i = 0; i < 8; i++)
        g_attn[rowoff + tid + i * 256] = __float2half(v[i] * inv);
}

// ---------------- launch ----------------------------------------------------
// scores stays at launch idx 3 so the fixed ncu window keeps profiling it.
extern "C" void kernel_launch(void* const* d_in, const int* in_sizes, int n_in,
                              void* d_out, int out_size)
{
    const float* x  = (const float*)d_in[0];
    const float* Wq = (const float*)d_in[1];
    const float* Wk = (const float*)d_in[2];
    const float* Wv = (const float*)d_in[3];
    float* out = (float*)d_out;

    cudaFuncSetAttribute(k_gemm_proj,   cudaFuncAttributeMaxDynamicSharedMemorySize, SMEM_TOTAL);
    cudaFuncSetAttribute(k_gemm_scores, cudaFuncAttributeMaxDynamicSharedMemorySize, SMEM_TOTAL);
    cudaFuncSetAttribute(k_gemm_av,     cudaFuncAttributeMaxDynamicSharedMemorySize, SMEM_TOTAL);

    k_addpe<<<((size_t)MTOT * FDIM) / 256, 256>>>(x);                            // 0
    k_transW<<<dim3(DDIM / 32, FDIM / 32, 3), 256>>>(Wq, Wk, Wv);               // 1
    k_gemm_proj<<<dim3(DDIM / 128, MTOT / 128, 3), 256, SMEM_TOTAL>>>();        // 2
    k_gemm_scores<<<dim3(SEQ / 128, SEQ / 128, BATCH), 256, SMEM_TOTAL>>>();    // 3 <- ncu
    k_transV<<<dim3(DDIM / 32, SEQ / 32, BATCH), 256>>>();                      // 4
    k_softmax<<<BATCH * SEQ, 256>>>();                                           // 5
    k_gemm_av<<<dim3(DDIM / 128, SEQ / 128, BATCH), 256, SMEM_TOTAL>>>(out);    // 6
}

// round 16
// speedup vs baseline: 6.2676x; 1.1702x over previous
#include <cuda_runtime.h>
#include <cuda_fp16.h>
#include <math.h>
#include <stdint.h>

#define BATCH 8
#define SEQ   2048
#define FDIM  512
#define DDIM  512
#define MTOT  (BATCH * SEQ)   // 16384

// ---------------- scratch (__device__ globals; no allocs allowed) ----------
__device__ __half g_xpe[(size_t)MTOT * FDIM];
__device__ __half g_Wt[3 * FDIM * DDIM];      // [z][n][k] (W transposed)
__device__ __half g_Q[(size_t)MTOT * DDIM];
__device__ __half g_K[(size_t)MTOT * DDIM];
__device__ __half g_V[(size_t)MTOT * DDIM];
__device__ __half g_Vt[(size_t)MTOT * DDIM];  // [b][d][j]
__device__ float  g_scores[(size_t)BATCH * SEQ * SEQ];     // 134MB
__device__ __half g_attn[(size_t)BATCH * SEQ * SEQ];

// ---------------- PTX helpers ----------------------------------------------
__device__ __forceinline__ uint32_t s2u(const void* p) {
    return (uint32_t)__cvta_generic_to_shared(p);
}
__device__ __forceinline__ void cpa16(uint32_t dst, const void* src) {
    asm volatile("cp.async.cg.shared.global [%0], [%1], 16;\n" :: "r"(dst), "l"(src));
}
#define CP_COMMIT()  asm volatile("cp.async.commit_group;\n" ::: "memory")
#define CP_WAIT1()   asm volatile("cp.async.wait_group 1;\n" ::: "memory")

#define LDM4(r, addr) \
    asm volatile("ldmatrix.sync.aligned.m8n8.x4.shared.b16 {%0,%1,%2,%3}, [%4];" \
                 : "=r"((r)[0]), "=r"((r)[1]), "=r"((r)[2]), "=r"((r)[3]) : "r"(addr))

#define MMA16816(d, a, b0, b1) \
    asm volatile("mma.sync.aligned.m16n8k16.row.col.f32.f16.f16.f32 " \
                 "{%0,%1,%2,%3}, {%4,%5,%6,%7}, {%8,%9}, {%0,%1,%2,%3};" \
                 : "+f"((d)[0]), "+f"((d)[1]), "+f"((d)[2]), "+f"((d)[3]) \
                 : "r"((a)[0]), "r"((a)[1]), "r"((a)[2]), "r"((a)[3]), \
                   "r"(b0), "r"(b1))

// ---------------- GEMM: CTA 128x128, K-chunk 64, fp16 1-term, HMMA ---------
// Rows are 64 fp16 = 128B data + 16B pad = 144B. Halving the chunk count
// (vs K32) halves the fitted ~48us per-chunk overhead term.
#define PLANE_B    18432               // 128 rows x 144B
#define STAGE_B    36864               // 2 planes (A, B)
#define SMEM_TOTAL (2 * STAGE_B)       // 73728 -> 2 CTAs/SM

__device__ __forceinline__ void ld_stage(uint32_t sb,
    const __half* A, const __half* B,
    int K, int k0, int tid)
{
#pragma unroll
    for (int i = 0; i < 4; i++) {
        int ci = tid + i * 256;        // 1024 16B-chunks per plane
        int r = ci >> 3, c = ci & 7;
        size_t ge = (size_t)r * K + k0 + c * 8;   // fp16 element offset
        uint32_t so = r * 144 + c * 16;
        cpa16(sb + so,           A + ge);
        cpa16(sb + PLANE_B + so, B + ge);
    }
}

// EPI 0: fp32 C with alpha.  EPI 1: fp16 plane.
template <int EPI>
__device__ __forceinline__ void gemm_core(
    const __half* __restrict__ A, const __half* __restrict__ B,
    int K, float alpha,
    float* __restrict__ C, int ldC,
    __half* __restrict__ Ch)
{
    extern __shared__ __align__(128) char sm[];
    const uint32_t smb = s2u(sm);
    const int tid = threadIdx.x;
    const int w = tid >> 5, lane = tid & 31;
    const int wr = w & 1, wc = w >> 1;         // warp grid 2 (M) x 4 (N)
    const int q = lane & 7, sel = lane >> 3;   // ldmatrix addressing
    const int g = lane >> 2, t = lane & 3;     // fragment addressing

    uint32_t aoff[4], boff[2];
#pragma unroll
    for (int mt = 0; mt < 4; mt++)
        aoff[mt] = (uint32_t)(wr * 64 + mt * 16 + (sel & 1) * 8 + q) * 144
                 + (uint32_t)(sel >> 1) * 16;
#pragma unroll
    for (int nb = 0; nb < 2; nb++)
        boff[nb] = (uint32_t)(wc * 32 + nb * 16 + (sel >> 1) * 8 + q) * 144
                 + (uint32_t)(sel & 1) * 16;

    const int n = K >> 6;   // K / 64 chunks

    ld_stage(smb, A, B, K, 0, tid); CP_COMMIT();

    float acc[4][4][4];
#pragma unroll
    for (int mt = 0; mt < 4; mt++)
#pragma unroll
        for (int nt = 0; nt < 4; nt++)
#pragma unroll
            for (int r = 0; r < 4; r++) acc[mt][nt][r] = 0.0f;

    for (int i = 0; i < n; i++) {
        if (i + 1 < n)
            ld_stage(smb + ((i + 1) & 1) * STAGE_B, A, B, K, (i + 1) * 64, tid);
        CP_COMMIT();
        CP_WAIT1();        // stage i resident; load(i+1) still in flight
        __syncthreads();

        const uint32_t sb = smb + (i & 1) * STAGE_B;
#pragma unroll
        for (int ks = 0; ks < 4; ks++) {
            uint32_t ah[4][4], bh[2][4];
#pragma unroll
            for (int mt = 0; mt < 4; mt++)
                LDM4(ah[mt], sb + aoff[mt] + ks * 32);
#pragma unroll
            for (int nb = 0; nb < 2; nb++)
                LDM4(bh[nb], sb + PLANE_B + boff[nb] + ks * 32);
#pragma unroll
            for (int mt = 0; mt < 4; mt++)
#pragma unroll
                for (int nt = 0; nt < 4; nt++) {
                    const uint32_t* B0 = &bh[nt >> 1][(nt & 1) * 2];
                    MMA16816(acc[mt][nt], ah[mt], B0[0], B0[1]);
                }
        }
        __syncthreads();   // release buffer (i&1)
    }

    // epilogue
#pragma unroll
    for (int mt = 0; mt < 4; mt++)
#pragma unroll
        for (int nt = 0; nt < 4; nt++) {
            int r0 = wr * 64 + mt * 16 + g;
            int c0 = wc * 32 + nt * 8 + 2 * t;
            if (EPI == 0) {
                float2 v0, v1;
                v0.x = alpha * acc[mt][nt][0]; v0.y = alpha * acc[mt][nt][1];
                v1.x = alpha * acc[mt][nt][2]; v1.y = alpha * acc[mt][nt][3];
                *(float2*)(C + (size_t)r0 * ldC + c0)       = v0;
                *(float2*)(C + (size_t)(r0 + 8) * ldC + c0) = v1;
            } else {
#pragma unroll
                for (int hh = 0; hh < 2; hh++) {
                    __half2 hp;
                    hp.x = __float2half(acc[mt][nt][2 * hh + 0]);
                    hp.y = __float2half(acc[mt][nt][2 * hh + 1]);
                    *(__half2*)(Ch + (size_t)(r0 + 8 * hh) * ldC + c0) = hp;
                }
            }
        }
}

// ---------------- GEMM wrapper kernels -------------------------------------
__global__ void __launch_bounds__(256, 2) k_gemm_proj() {
    const int z = blockIdx.z;
    const size_t a0 = (size_t)blockIdx.y * 128 * FDIM;
    const size_t b0 = (size_t)z * FDIM * DDIM + (size_t)blockIdx.x * 128 * FDIM;
    __half* Cz = (z == 0) ? g_Q : (z == 1) ? g_K : g_V;
    const size_t c0 = (size_t)blockIdx.y * 128 * DDIM + blockIdx.x * 128;
    gemm_core<1>(g_xpe + a0, g_Wt + b0, FDIM, 1.0f, nullptr, DDIM, Cz + c0);
}

__global__ void __launch_bounds__(256, 2) k_gemm_scores() {
    const size_t b = blockIdx.z;
    const size_t a0 = b * SEQ * DDIM + (size_t)blockIdx.y * 128 * DDIM;
    const size_t b0 = b * SEQ * DDIM + (size_t)blockIdx.x * 128 * DDIM;
    const size_t c0 = b * SEQ * SEQ + (size_t)blockIdx.y * 128 * SEQ + blockIdx.x * 128;
    gemm_core<0>(g_Q + a0, g_K + b0,
                 DDIM, 0.04419417382415922f, g_scores + c0, SEQ, nullptr);
}

__global__ void __launch_bounds__(256, 2) k_gemm_av(float* __restrict__ out) {
    const size_t b = blockIdx.z;
    const size_t a0 = b * SEQ * SEQ + (size_t)blockIdx.y * 128 * SEQ;
    const size_t b0 = b * DDIM * SEQ + (size_t)blockIdx.x * 128 * SEQ;
    const size_t c0 = b * SEQ * DDIM + (size_t)blockIdx.y * 128 * DDIM + blockIdx.x * 128;
    gemm_core<0>(g_attn + a0, g_Vt + b0, SEQ, 1.0f, out + c0, DDIM, nullptr);
}

// ---------------- aux kernels ----------------------------------------------
// fp32 Cody-Waite 2-term range reduction (error ~2e-7, no fp64 pipe).
__global__ void __launch_bounds__(256) k_addpe(const float* __restrict__ x) {
    size_t idx = (size_t)blockIdx.x * 256 + threadIdx.x;
    int f = (int)(idx & (FDIM - 1));
    int s = (int)((idx >> 9) & (SEQ - 1));
    float e     = (float)(f & ~1) * (1.0f / (float)FDIM);
    float denom = powf(10000.0f, e);
    float angle = (float)s / denom;
    const float TWO_PI_HI = 6.28318548202514648f;
    const float TWO_PI_LO = -1.7484555e-7f;
    float nq = rintf(angle * 0.15915493667125702f);
    float a = fmaf(-nq, TWO_PI_HI, angle);
    a = fmaf(-nq, TWO_PI_LO, a);
    float pe = (f & 1) ? cosf(a) : sinf(a);
    g_xpe[idx] = __float2half(x[idx] + pe);
}

// transpose W: Wt[z][n][k] = W[z][k][n]
__global__ void __launch_bounds__(256) k_transW(const float* __restrict__ Wq,
                                                const float* __restrict__ Wk,
                                                const float* __restrict__ Wv) {
    __shared__ float tsm[32][33];
    const int z = blockIdx.z;
    const float* W = (z == 0) ? Wq : (z == 1) ? Wk : Wv;
    const int k0 = blockIdx.y * 32, n0 = blockIdx.x * 32;
    const int tx = threadIdx.x & 31, ty = threadIdx.x >> 5;  // 32 x 8
#pragma unroll
    for (int i = 0; i < 32; i += 8)
        tsm[ty + i][tx] = W[(size_t)(k0 + ty + i) * DDIM + n0 + tx];
    __syncthreads();
#pragma unroll
    for (int i = 0; i < 32; i += 8) {
        size_t off = (size_t)z * FDIM * DDIM + (size_t)(n0 + ty + i) * FDIM + k0 + tx;
        g_Wt[off] = __float2half(tsm[tx][ty + i]);
    }
}

// transpose V: Vt[b][d][j] = V[b*2048+j][d]
__global__ void __launch_bounds__(256) k_transV() {
    __shared__ __half th[32][33];
    const int b = blockIdx.z;
    const int d0 = blockIdx.x * 32, j0 = blockIdx.y * 32;
    const int tx = threadIdx.x & 31, ty = threadIdx.x >> 5;
#pragma unroll
    for (int i = 0; i < 32; i += 8) {
        size_t off = (size_t)(b * SEQ + j0 + ty + i) * DDIM + d0 + tx;
        th[ty + i][tx] = g_V[off];
    }
    __syncthreads();
#pragma unroll
    for (int i = 0; i < 32; i += 8) {
        size_t off = (size_t)b * DDIM * SEQ + (size_t)(d0 + ty + i) * SEQ + j0 + tx;
        g_Vt[off] = th[tx][ty + i];
    }
}

// softmax over 2048 cols -> fp16 attn (vectorized: thread owns 8 contiguous)
__global__ void __launch_bounds__(256) k_softmax() {
    const size_t rowoff = (size_t)blockIdx.x * SEQ;
    const int tid = threadIdx.x;
    const float4* p4 = (const float4*)(g_scores + rowoff + tid * 8);
    float4 A = p4[0], Bv = p4[1];
    float v[8] = {A.x, A.y, A.z, A.w, Bv.x, Bv.y, Bv.z, Bv.w};

    float m = -1e30f;
#pragma unroll
    for (int i = 0; i < 8; i++) m = fmaxf(m, v[i]);
    __shared__ float sh[8];
#pragma unroll
    for (int o = 16; o > 0; o >>= 1)
        m = fmaxf(m, __shfl_xor_sync(0xffffffffu, m, o));
    if ((tid & 31) == 0) sh[tid >> 5] = m;
    __syncthreads();
    m = sh[0];
#pragma unroll
    for (int w = 1; w < 8; w++) m = fmaxf(m, sh[w]);

    float s = 0.0f;
#pragma unroll
    for (int i = 0; i < 8; i++) {
        v[i] = expf(v[i] - m);
        s += v[i];
    }
#pragma unroll
    for (int o = 16; o > 0; o >>= 1)
        s += __shfl_xor_sync(0xffffffffu, s, o);
    __syncthreads();
    if ((tid & 31) == 0) sh[tid >> 5] = s;
    __syncthreads();
    s = 0.0f;
#pragma unroll
    for (int w = 0; w < 8; w++) s += sh[w];
    const float inv = 1.0f / s;

    __half2* o2 = (__half2*)(g_attn + rowoff + tid * 8);
#pragma unroll
    for (int i = 0; i < 4; i++) {
        __half2 hp;
        hp.x = __float2half(v[2 * i + 0] * inv);
        hp.y = __float2half(v[2 * i + 1] * inv);
        o2[i] = hp;
    }
}

// ---------------- launch ----------------------------------------------------
// scores stays at launch idx 3 so the fixed ncu window keeps profiling it.
extern "C" void kernel_launch(void* const* d_in, const int* in_sizes, int n_in,
                              void* d_out, int out_size)
{
    const float* x  = (const float*)d_in[0];
    const float* Wq = (const float*)d_in[1];
    const float* Wk = (const float*)d_in[2];
    const float* Wv = (const float*)d_in[3];
    float* out = (float*)d_out;

    cudaFuncSetAttribute(k_gemm_proj,   cudaFuncAttributeMaxDynamicSharedMemorySize, SMEM_TOTAL);
    cudaFuncSetAttribute(k_gemm_scores, cudaFuncAttributeMaxDynamicSharedMemorySize, SMEM_TOTAL);
    cudaFuncSetAttribute(k_gemm_av,     cudaFuncAttributeMaxDynamicSharedMemorySize, SMEM_TOTAL);

    k_addpe<<<((size_t)MTOT * FDIM) / 256, 256>>>(x);                            // 0
    k_transW<<<dim3(DDIM / 32, FDIM / 32, 3), 256>>>(Wq, Wk, Wv);               // 1
    k_gemm_proj<<<dim3(DDIM / 128, MTOT / 128, 3), 256, SMEM_TOTAL>>>();        // 2
    k_gemm_scores<<<dim3(SEQ / 128, SEQ / 128, BATCH), 256, SMEM_TOTAL>>>();    // 3 <- ncu
    k_transV<<<dim3(DDIM / 32, SEQ / 32, BATCH), 256>>>();                      // 4
    k_softmax<<<BATCH * SEQ, 256>>>();                                           // 5
    k_gemm_av<<<dim3(DDIM / 128, SEQ / 128, BATCH), 256, SMEM_TOTAL>>>(out);    // 6
}